// round 1
// baseline (speedup 1.0000x reference)
#include <cuda_runtime.h>
#include <cuda_bf16.h>
#include <cstdint>

// ---------------- Problem constants ----------------
#define B_    16384
#define F_    26
#define V_    100000
#define E_    16
#define CONT_ 13
#define K1_   429      // CONT_ + F_*E_
#define LDA_  432      // K1_ padded to /8 for float4 + BK=8 loop
#define H_    400      // H1 == H2

// ---------------- Scratch (device globals; no allocation allowed) ----------------
__device__ float g_dnn[(size_t)B_ * LDA_];   // [B, 432] : [cont(13) | emb(416) | pad(3)=0]
__device__ float g_fm [B_];                  // fm_out per row
__device__ float g_h1 [(size_t)B_ * H_];     // relu(dnn_in @ W1 + b1)
__device__ float g_h2 [(size_t)B_ * H_];     // relu(h1 @ W2 + b2)

// ============================================================================
// Kernel 1: one warp per sample.
//   lane f (<26): gathers emb row [16 floats], writes to dnn_in, accumulates
//                 per-lane vector v (== field's emb vector), q = sum(v^2),
//                 scal = first_order[f] (+ cont[l]*w_cont[l] for lanes <13).
//   butterfly-reduce v[16], q, scal across lanes ->
//   fm = scal + b_cont + 0.5*(sum_e S_e^2 - q)
// ============================================================================
__global__ void gather_fm_kernel(const float* __restrict__ cont,
                                 const int*   __restrict__ cat,
                                 const float* __restrict__ w_cont,
                                 const float* __restrict__ b_cont,
                                 const float* __restrict__ t_first,
                                 const float* __restrict__ t_emb) {
    int warp = (blockIdx.x * blockDim.x + threadIdx.x) >> 5;
    int lane = threadIdx.x & 31;
    if (warp >= B_) return;
    const int b = warp;

    float v[16];
    #pragma unroll
    for (int i = 0; i < 16; i++) v[i] = 0.f;
    float q = 0.f, scal = 0.f;

    if (lane < F_) {
        int idx = cat[b * F_ + lane];
        const float4* row =
            reinterpret_cast<const float4*>(t_emb + ((size_t)lane * V_ + (size_t)idx) * E_);
        float4 r0 = row[0], r1 = row[1], r2 = row[2], r3 = row[3];
        v[0]=r0.x; v[1]=r0.y; v[2]=r0.z; v[3]=r0.w;
        v[4]=r1.x; v[5]=r1.y; v[6]=r1.z; v[7]=r1.w;
        v[8]=r2.x; v[9]=r2.y; v[10]=r2.z; v[11]=r2.w;
        v[12]=r3.x; v[13]=r3.y; v[14]=r3.z; v[15]=r3.w;

        float* dst = g_dnn + (size_t)b * LDA_ + CONT_ + lane * E_;
        #pragma unroll
        for (int i = 0; i < 16; i++) {
            dst[i] = v[i];
            q = fmaf(v[i], v[i], q);
        }
        scal = t_first[(size_t)lane * V_ + (size_t)idx];
    }
    if (lane < CONT_) {
        float c = cont[b * CONT_ + lane];
        g_dnn[(size_t)b * LDA_ + lane] = c;
        scal = fmaf(c, w_cont[lane], scal);
    }
    if (lane >= 29) {  // zero pad columns 429..431
        g_dnn[(size_t)b * LDA_ + K1_ + (lane - 29)] = 0.f;
    }

    // butterfly reduce: v[16] (vector sum S_e), q, scal
    #pragma unroll
    for (int off = 16; off; off >>= 1) {
        #pragma unroll
        for (int e = 0; e < 16; e++)
            v[e] += __shfl_xor_sync(0xffffffffu, v[e], off);
        q    += __shfl_xor_sync(0xffffffffu, q,    off);
        scal += __shfl_xor_sync(0xffffffffu, scal, off);
    }

    if (lane == 0) {
        float ss = 0.f;
        #pragma unroll
        for (int e = 0; e < 16; e++) ss = fmaf(v[e], v[e], ss);
        g_fm[b] = scal + b_cont[0] + 0.5f * (ss - q);
    }
}

// ============================================================================
// Kernel 2/3: classic 128x128x8 SGEMM, 256 threads, 8x8 register tile.
//   C[M,N] = act(A[M,Kloop](lda) @ W[Kb,N] + bias)   (W rows >= Kb are zero)
//   Kloop is padded-to-8 K; Kb is the true K for guarding W loads.
// ============================================================================
template<bool RELU>
__global__ void __launch_bounds__(256, 2)
sgemm_bias_act(const float* __restrict__ A, int lda,
               const float* __restrict__ Bw,   // [Kb, N] row-major
               const float* __restrict__ bias,
               float* __restrict__ C, int ldc,
               int N, int Kloop, int Kb) {
    constexpr int BM = 128, BN = 128, BK = 8, TM = 8, TN = 8;
    __shared__ float As[BK][BM];
    __shared__ float Bs[BK][BN];

    const int tid = threadIdx.x;
    const int tx  = tid & 15;        // 0..15 -> N
    const int ty  = tid >> 4;        // 0..15 -> M
    const int bx  = blockIdx.x;      // N tile
    const int by  = blockIdx.y;      // M tile

    const int a_row = tid >> 1;            // 0..127
    const int a_col = (tid & 1) << 2;      // 0 or 4
    const int b_row = tid >> 5;            // 0..7
    const int b_col = (tid & 31) << 2;     // 0..124

    const float* Aptr = A + (size_t)(by * BM + a_row) * lda + a_col;
    const int bn = bx * BN + b_col;
    const bool bn_ok = (bn < N);           // N%4==0 -> whole float4 valid

    float acc[TM][TN];
    #pragma unroll
    for (int i = 0; i < TM; i++)
        #pragma unroll
        for (int j = 0; j < TN; j++) acc[i][j] = 0.f;

    for (int k0 = 0; k0 < Kloop; k0 += BK) {
        float4 av = *reinterpret_cast<const float4*>(Aptr + k0);
        As[a_col + 0][a_row] = av.x;
        As[a_col + 1][a_row] = av.y;
        As[a_col + 2][a_row] = av.z;
        As[a_col + 3][a_row] = av.w;

        float4 bv = make_float4(0.f, 0.f, 0.f, 0.f);
        int kb = k0 + b_row;
        if (bn_ok && kb < Kb)
            bv = *reinterpret_cast<const float4*>(Bw + (size_t)kb * N + bn);
        *reinterpret_cast<float4*>(&Bs[b_row][b_col]) = bv;

        __syncthreads();

        #pragma unroll
        for (int kk = 0; kk < BK; kk++) {
            float ar[TM], br[TN];
            #pragma unroll
            for (int i = 0; i < TM; i++) ar[i] = As[kk][ty * TM + i];
            #pragma unroll
            for (int j = 0; j < TN; j++) br[j] = Bs[kk][tx * TN + j];
            #pragma unroll
            for (int i = 0; i < TM; i++)
                #pragma unroll
                for (int j = 0; j < TN; j++)
                    acc[i][j] = fmaf(ar[i], br[j], acc[i][j]);
        }
        __syncthreads();
    }

    const int n0 = bx * BN + tx * TN;
    if (n0 < N) {                       // N%8==0 -> whole 8-span valid
        const int m0 = by * BM + ty * TM;
        float bs[TN];
        #pragma unroll
        for (int j = 0; j < TN; j++) bs[j] = bias[n0 + j];
        #pragma unroll
        for (int i = 0; i < TM; i++) {
            float* crow = C + (size_t)(m0 + i) * ldc + n0;
            #pragma unroll
            for (int j = 0; j < TN; j++) {
                float x = acc[i][j] + bs[j];
                if (RELU) x = fmaxf(x, 0.f);
                crow[j] = x;
            }
        }
    }
}

// ============================================================================
// Kernel 4: one warp per sample.
//   out[b] = fm[b]*W_out[0] + b_out + sum_j h2[b][j]*W_out[1+j]
// ============================================================================
__global__ void final_kernel(const float* __restrict__ Wout,
                             const float* __restrict__ bout,
                             float* __restrict__ out) {
    int warp = (blockIdx.x * blockDim.x + threadIdx.x) >> 5;
    int lane = threadIdx.x & 31;
    if (warp >= B_) return;

    const float* h = g_h2 + (size_t)warp * H_;
    float s = 0.f;
    #pragma unroll 4
    for (int j = lane; j < H_; j += 32)
        s = fmaf(h[j], Wout[1 + j], s);
    #pragma unroll
    for (int off = 16; off; off >>= 1)
        s += __shfl_xor_sync(0xffffffffu, s, off);

    if (lane == 0)
        out[warp] = fmaf(g_fm[warp], Wout[0], bout[0] + s);
}

// ============================================================================
// Launch
// ============================================================================
static float* sym_addr(const void* symbol) {
    void* p = nullptr;
    cudaGetSymbolAddress(&p, symbol);
    return (float*)p;
}

extern "C" void kernel_launch(void* const* d_in, const int* in_sizes, int n_in,
                              void* d_out, int out_size) {
    const float* cont    = (const float*)d_in[0];
    const int*   cat     = (const int*)  d_in[1];
    const float* w_cont  = (const float*)d_in[2];
    const float* b_cont  = (const float*)d_in[3];
    const float* t_first = (const float*)d_in[4];
    const float* t_emb   = (const float*)d_in[5];
    const float* W1      = (const float*)d_in[6];
    const float* b1      = (const float*)d_in[7];
    const float* W2      = (const float*)d_in[8];
    const float* b2      = (const float*)d_in[9];
    const float* Wout    = (const float*)d_in[10];
    const float* bout    = (const float*)d_in[11];
    float* out = (float*)d_out;

    float* dnn = sym_addr(g_dnn);
    float* h1  = sym_addr(g_h1);
    float* h2  = sym_addr(g_h2);

    // 1) gather + FM + dnn_in materialization
    gather_fm_kernel<<<B_ / 8, 256>>>(cont, cat, w_cont, b_cont, t_first, t_emb);

    // 2) h1 = relu(dnn_in @ W1 + b1)   (Kloop=432 padded, W guard Kb=429)
    dim3 grid1((H_ + 127) / 128, B_ / 128);
    sgemm_bias_act<true><<<grid1, 256>>>(dnn, LDA_, W1, b1, h1, H_, H_, LDA_, K1_);

    // 3) h2 = relu(h1 @ W2 + b2)
    sgemm_bias_act<true><<<grid1, 256>>>(h1, H_, W2, b2, h2, H_, H_, H_, H_);

    // 4) out = fm*W_out[0] + h2 . W_out[1:] + b_out
    final_kernel<<<B_ / 8, 256>>>(Wout, bout, out);
}

// round 2
// speedup vs baseline: 1.5469x; 1.5469x over previous
#include <cuda_runtime.h>
#include <cuda_bf16.h>
#include <cstdint>

// ---------------- Problem constants ----------------
#define B_    16384
#define F_    26
#define V_    100000
#define E_    16
#define CONT_ 13
#define K1_   429      // CONT_ + F_*E_
#define LDA_  432      // K1_ padded to multiple of 16
#define H_    400      // H1 == H2

// ---------------- Scratch (device globals) ----------------
__device__ float g_dnn [(size_t)B_ * LDA_];  // [B, 432] : [cont | emb | pad=0]
__device__ float g_fm  [B_];                 // fm_out per row
__device__ float g_h1  [(size_t)B_ * H_];    // relu(dnn_in @ W1 + b1)
__device__ float g_part[4][B_];              // per-N-block partial dots (GEMM2 fused)

// ============================================================================
// Kernel 1: gather + FM + dnn_in materialization (one warp per sample)
// ============================================================================
__global__ void gather_fm_kernel(const float* __restrict__ cont,
                                 const int*   __restrict__ cat,
                                 const float* __restrict__ w_cont,
                                 const float* __restrict__ b_cont,
                                 const float* __restrict__ t_first,
                                 const float* __restrict__ t_emb) {
    int warp = (blockIdx.x * blockDim.x + threadIdx.x) >> 5;
    int lane = threadIdx.x & 31;
    if (warp >= B_) return;
    const int b = warp;

    float v[16];
    #pragma unroll
    for (int i = 0; i < 16; i++) v[i] = 0.f;
    float q = 0.f, scal = 0.f;

    if (lane < F_) {
        int idx = cat[b * F_ + lane];
        const float4* row =
            reinterpret_cast<const float4*>(t_emb + ((size_t)lane * V_ + (size_t)idx) * E_);
        float4 r0 = row[0], r1 = row[1], r2 = row[2], r3 = row[3];
        v[0]=r0.x; v[1]=r0.y; v[2]=r0.z; v[3]=r0.w;
        v[4]=r1.x; v[5]=r1.y; v[6]=r1.z; v[7]=r1.w;
        v[8]=r2.x; v[9]=r2.y; v[10]=r2.z; v[11]=r2.w;
        v[12]=r3.x; v[13]=r3.y; v[14]=r3.z; v[15]=r3.w;

        float* dst = g_dnn + (size_t)b * LDA_ + CONT_ + lane * E_;
        #pragma unroll
        for (int i = 0; i < 16; i++) {
            dst[i] = v[i];
            q = fmaf(v[i], v[i], q);
        }
        scal = t_first[(size_t)lane * V_ + (size_t)idx];
    }
    if (lane < CONT_) {
        float c = cont[b * CONT_ + lane];
        g_dnn[(size_t)b * LDA_ + lane] = c;
        scal = fmaf(c, w_cont[lane], scal);
    }
    if (lane >= 29) {  // zero pad columns 429..431
        g_dnn[(size_t)b * LDA_ + K1_ + (lane - 29)] = 0.f;
    }

    #pragma unroll
    for (int off = 16; off; off >>= 1) {
        #pragma unroll
        for (int e = 0; e < 16; e++)
            v[e] += __shfl_xor_sync(0xffffffffu, v[e], off);
        q    += __shfl_xor_sync(0xffffffffu, q,    off);
        scal += __shfl_xor_sync(0xffffffffu, scal, off);
    }

    if (lane == 0) {
        float ss = 0.f;
        #pragma unroll
        for (int e = 0; e < 16; e++) ss = fmaf(v[e], v[e], ss);
        g_fm[b] = scal + b_cont[0] + 0.5f * (ss - q);
    }
}

// ============================================================================
// TF32 helpers
// ============================================================================
__device__ __forceinline__ uint32_t f2tf32(float x) {
    uint32_t r;
    asm("cvt.rna.tf32.f32 %0, %1;" : "=r"(r) : "f"(x));
    return r;
}
__device__ __forceinline__ void mma_tf32(float* c,
                                         uint32_t a0, uint32_t a1, uint32_t a2, uint32_t a3,
                                         uint32_t b0, uint32_t b1) {
    asm volatile(
        "mma.sync.aligned.m16n8k8.row.col.f32.tf32.tf32.f32 "
        "{%0,%1,%2,%3},{%4,%5,%6,%7},{%8,%9},{%0,%1,%2,%3};"
        : "+f"(c[0]), "+f"(c[1]), "+f"(c[2]), "+f"(c[3])
        : "r"(a0), "r"(a1), "r"(a2), "r"(a3), "r"(b0), "r"(b1));
}

#define CP_ASYNC16(smem_u32, gptr) \
    asm volatile("cp.async.cg.shared.global [%0], [%1], 16;" :: "r"(smem_u32), "l"(gptr))
#define CP_ASYNC16_Z(smem_u32, gptr, sz) \
    asm volatile("cp.async.cg.shared.global [%0], [%1], 16, %2;" :: "r"(smem_u32), "l"(gptr), "r"(sz))
#define CP_COMMIT() asm volatile("cp.async.commit_group;")
#define CP_WAIT1()  asm volatile("cp.async.wait_group 1;")

// ============================================================================
// 3xTF32 GEMM: C[M,N] = relu(A[M,Kloop](lda) @ W[Kb,N] + bias)
//   BM=128, BN=128, BK=16; 256 threads; warp tile 64x32 (m16n8k8 mma)
//   FUSE=1: instead of storing C, compute partial dot with Wout into g_part.
// ============================================================================
template<bool FUSE>
__global__ void __launch_bounds__(256, 1)
gemm_tf32(const float* __restrict__ A, int lda,
          const float* __restrict__ W,      // [Kb, N] row-major (rows >= Kb treated 0)
          const float* __restrict__ bias,   // [N]
          float* __restrict__ C,            // [M, N] (FUSE=0)
          const float* __restrict__ Wout,   // [1+N] (FUSE=1; uses Wout[1+n])
          int N, int Kloop, int Kb) {
    constexpr int BM = 128, BN = 128, BK = 16;
    __shared__ float As[2][BM][20];     // stride 20: conflict-free frag reads
    __shared__ float Bs[2][BK][136];    // stride 136: conflict-free frag reads
    __shared__ float part[4][BM];

    const int tid  = threadIdx.x;
    const int warp = tid >> 5, lane = tid & 31;
    const int gr = lane >> 2, gc = lane & 3;
    const int wm = (warp >> 2) * 64;    // warp row offset within CTA (0/64)
    const int wn = (warp & 3) * 32;     // warp col offset within CTA (0..96)
    const int m0 = blockIdx.y * BM;
    const int n0 = blockIdx.x * BN;

    float acc[4][4][4];
    #pragma unroll
    for (int i = 0; i < 4; i++)
        #pragma unroll
        for (int j = 0; j < 4; j++)
            #pragma unroll
            for (int k = 0; k < 4; k++) acc[i][j][k] = 0.f;

    const int iters = Kloop / BK;

    // ---- tile loader (all 256 threads; 2 float4 each for A and B) ----
    #define LOAD_TILE(IT, BUF)                                                        \
    do {                                                                              \
        int k0_ = (IT) * BK;                                                          \
        _Pragma("unroll")                                                             \
        for (int h = 0; h < 2; h++) {                                                 \
            int c_ = tid + h * 256;                                                   \
            int ar_ = c_ >> 2, ak_ = (c_ & 3) << 2;                                   \
            const float* gp_ = A + (size_t)(m0 + ar_) * lda + k0_ + ak_;              \
            uint32_t sa_ = (uint32_t)__cvta_generic_to_shared(&As[BUF][ar_][ak_]);    \
            CP_ASYNC16(sa_, gp_);                                                     \
        }                                                                             \
        _Pragma("unroll")                                                             \
        for (int h = 0; h < 2; h++) {                                                 \
            int c_ = tid + h * 256;                                                   \
            int bk_ = c_ >> 5, bn_ = (c_ & 31) << 2;                                  \
            int gk_ = k0_ + bk_, gn_ = n0 + bn_;                                      \
            bool ok_ = (gk_ < Kb) && (gn_ < N);                                       \
            const float* gp_ = W + (size_t)(ok_ ? gk_ : 0) * N + (ok_ ? gn_ : 0);     \
            uint32_t sa_ = (uint32_t)__cvta_generic_to_shared(&Bs[BUF][bk_][bn_]);    \
            int sz_ = ok_ ? 16 : 0;                                                   \
            CP_ASYNC16_Z(sa_, gp_, sz_);                                              \
        }                                                                             \
    } while (0)

    LOAD_TILE(0, 0);
    CP_COMMIT();

    for (int it = 0; it < iters; ++it) {
        int buf = it & 1;
        if (it + 1 < iters) LOAD_TILE(it + 1, buf ^ 1);
        CP_COMMIT();
        CP_WAIT1();
        __syncthreads();

        #pragma unroll
        for (int ks = 0; ks < 2; ks++) {
            const int kb = ks * 8;
            uint32_t ah[4][4], al[4][4];
            #pragma unroll
            for (int mi = 0; mi < 4; mi++) {
                int r = wm + mi * 16 + gr;
                float f0 = As[buf][r    ][kb + gc];
                float f1 = As[buf][r + 8][kb + gc];
                float f2 = As[buf][r    ][kb + gc + 4];
                float f3 = As[buf][r + 8][kb + gc + 4];
                ah[mi][0] = f2tf32(f0); al[mi][0] = f2tf32(f0 - __uint_as_float(ah[mi][0]));
                ah[mi][1] = f2tf32(f1); al[mi][1] = f2tf32(f1 - __uint_as_float(ah[mi][1]));
                ah[mi][2] = f2tf32(f2); al[mi][2] = f2tf32(f2 - __uint_as_float(ah[mi][2]));
                ah[mi][3] = f2tf32(f3); al[mi][3] = f2tf32(f3 - __uint_as_float(ah[mi][3]));
            }
            uint32_t bh[4][2], bl[4][2];
            #pragma unroll
            for (int ni = 0; ni < 4; ni++) {
                int n = wn + ni * 8 + gr;
                float g0 = Bs[buf][kb + gc    ][n];
                float g1 = Bs[buf][kb + gc + 4][n];
                bh[ni][0] = f2tf32(g0); bl[ni][0] = f2tf32(g0 - __uint_as_float(bh[ni][0]));
                bh[ni][1] = f2tf32(g1); bl[ni][1] = f2tf32(g1 - __uint_as_float(bh[ni][1]));
            }
            #pragma unroll
            for (int mi = 0; mi < 4; mi++)
                #pragma unroll
                for (int ni = 0; ni < 4; ni++) {
                    mma_tf32(acc[mi][ni], ah[mi][0], ah[mi][1], ah[mi][2], ah[mi][3],
                             bh[ni][0], bh[ni][1]);
                    mma_tf32(acc[mi][ni], al[mi][0], al[mi][1], al[mi][2], al[mi][3],
                             bh[ni][0], bh[ni][1]);
                    mma_tf32(acc[mi][ni], ah[mi][0], ah[mi][1], ah[mi][2], ah[mi][3],
                             bl[ni][0], bl[ni][1]);
                }
        }
        __syncthreads();
    }
    #undef LOAD_TILE

    // ---- epilogue ----
    if (!FUSE) {
        #pragma unroll
        for (int mi = 0; mi < 4; mi++) {
            int r = m0 + wm + mi * 16 + gr;
            #pragma unroll
            for (int ni = 0; ni < 4; ni++) {
                int n = n0 + wn + ni * 8 + gc * 2;
                if (n < N) {
                    float b0v = bias[n], b1v = bias[n + 1];
                    float2 v0 = make_float2(fmaxf(acc[mi][ni][0] + b0v, 0.f),
                                            fmaxf(acc[mi][ni][1] + b1v, 0.f));
                    float2 v1 = make_float2(fmaxf(acc[mi][ni][2] + b0v, 0.f),
                                            fmaxf(acc[mi][ni][3] + b1v, 0.f));
                    *reinterpret_cast<float2*>(&C[(size_t)r * N + n])       = v0;
                    *reinterpret_cast<float2*>(&C[(size_t)(r + 8) * N + n]) = v1;
                }
            }
        }
    } else {
        #pragma unroll
        for (int mi = 0; mi < 4; mi++) {
            float s0 = 0.f, s1 = 0.f;
            #pragma unroll
            for (int ni = 0; ni < 4; ni++) {
                int n = n0 + wn + ni * 8 + gc * 2;
                float w0v = 0.f, w1v = 0.f, b0v = 0.f, b1v = 0.f;
                if (n < N) {
                    w0v = Wout[1 + n]; w1v = Wout[2 + n];
                    b0v = bias[n];     b1v = bias[n + 1];
                }
                s0 = fmaf(fmaxf(acc[mi][ni][0] + b0v, 0.f), w0v, s0);
                s0 = fmaf(fmaxf(acc[mi][ni][1] + b1v, 0.f), w1v, s0);
                s1 = fmaf(fmaxf(acc[mi][ni][2] + b0v, 0.f), w0v, s1);
                s1 = fmaf(fmaxf(acc[mi][ni][3] + b1v, 0.f), w1v, s1);
            }
            // quad reduce (over gc lanes)
            s0 += __shfl_xor_sync(0xffffffffu, s0, 1);
            s0 += __shfl_xor_sync(0xffffffffu, s0, 2);
            s1 += __shfl_xor_sync(0xffffffffu, s1, 1);
            s1 += __shfl_xor_sync(0xffffffffu, s1, 2);
            if (gc == 0) {
                part[warp & 3][wm + mi * 16 + gr]     = s0;
                part[warp & 3][wm + mi * 16 + gr + 8] = s1;
            }
        }
        __syncthreads();
        if (tid < BM) {
            float t = part[0][tid] + part[1][tid] + part[2][tid] + part[3][tid];
            g_part[blockIdx.x][m0 + tid] = t;
        }
    }
}

// ============================================================================
// Finish: out[b] = fm[b]*Wout[0] + b_out + sum_p g_part[p][b]
// ============================================================================
__global__ void finish_kernel(const float* __restrict__ Wout,
                              const float* __restrict__ bout,
                              float* __restrict__ out) {
    int b = blockIdx.x * blockDim.x + threadIdx.x;
    if (b >= B_) return;
    float s = g_part[0][b] + g_part[1][b] + g_part[2][b] + g_part[3][b];
    out[b] = fmaf(g_fm[b], Wout[0], bout[0] + s);
}

// ============================================================================
// Launch
// ============================================================================
static float* sym_addr(const void* symbol) {
    void* p = nullptr;
    cudaGetSymbolAddress(&p, symbol);
    return (float*)p;
}

extern "C" void kernel_launch(void* const* d_in, const int* in_sizes, int n_in,
                              void* d_out, int out_size) {
    const float* cont    = (const float*)d_in[0];
    const int*   cat     = (const int*)  d_in[1];
    const float* w_cont  = (const float*)d_in[2];
    const float* b_cont  = (const float*)d_in[3];
    const float* t_first = (const float*)d_in[4];
    const float* t_emb   = (const float*)d_in[5];
    const float* W1      = (const float*)d_in[6];
    const float* b1      = (const float*)d_in[7];
    const float* W2      = (const float*)d_in[8];
    const float* b2      = (const float*)d_in[9];
    const float* Wout    = (const float*)d_in[10];
    const float* bout    = (const float*)d_in[11];
    float* out = (float*)d_out;

    float* dnn = sym_addr(g_dnn);
    float* h1  = sym_addr(g_h1);

    // 1) gather + FM + dnn_in
    gather_fm_kernel<<<B_ / 8, 256>>>(cont, cat, w_cont, b_cont, t_first, t_emb);

    // 2) h1 = relu(dnn_in @ W1 + b1)   (3xTF32 tensor GEMM)
    dim3 grid((H_ + 127) / 128, B_ / 128);
    gemm_tf32<false><<<grid, 256>>>(dnn, LDA_, W1, b1, h1, nullptr, H_, LDA_, K1_);

    // 3) fused: h2 = relu(h1 @ W2 + b2); g_part = per-block dot(h2, Wout[1:])
    gemm_tf32<true><<<grid, 256>>>(h1, H_, W2, b2, nullptr, Wout, H_, H_, H_);

    // 4) out = fm*Wout[0] + b_out + sum(parts)
    finish_kernel<<<B_ / 256, 256>>>(Wout, bout, out);
}

// round 4
// speedup vs baseline: 2.3061x; 1.4908x over previous
#include <cuda_runtime.h>
#include <cuda_bf16.h>
#include <cstdint>

// ---------------- Problem constants ----------------
#define B_     16384
#define F_     26
#define V_     100000
#define E_     16
#define CONT_  13
#define K1_    429     // CONT_ + F_*E_
#define LDA1_  448     // K1_ padded to multiple of 32
#define K2PAD_ 416     // H_(400) padded to multiple of 32
#define NPAD_  512     // H_ padded to multiple of 128 (weight rows)
#define H_     400

// ---------------- Scratch (device globals) ----------------
__device__ __align__(256) __nv_bfloat16 g_dnnh[(size_t)B_ * LDA1_];
__device__ __align__(256) __nv_bfloat16 g_dnnl[(size_t)B_ * LDA1_];
__device__ __align__(256) __nv_bfloat16 g_h1h [(size_t)B_ * K2PAD_];
__device__ __align__(256) __nv_bfloat16 g_h1l [(size_t)B_ * K2PAD_];
__device__ __align__(256) __nv_bfloat16 g_w1th[(size_t)NPAD_ * LDA1_];   // [n][k] = W1[k][n]
__device__ __align__(256) __nv_bfloat16 g_w1tl[(size_t)NPAD_ * LDA1_];
__device__ __align__(256) __nv_bfloat16 g_w2th[(size_t)NPAD_ * K2PAD_];  // [n][k] = W2[k][n]
__device__ __align__(256) __nv_bfloat16 g_w2tl[(size_t)NPAD_ * K2PAD_];
__device__ float g_fm  [B_];
__device__ float g_part[4][B_];

// ---------------- PTX helpers ----------------
__device__ __forceinline__ uint32_t smem_u32(const void* p) {
    return (uint32_t)__cvta_generic_to_shared(p);
}
#define CP16(dst_u32, src) \
    asm volatile("cp.async.cg.shared.global [%0], [%1], 16;" :: "r"(dst_u32), "l"(src))
#define CP_COMMIT() asm volatile("cp.async.commit_group;" ::: "memory")
#define CP_WAIT0()  asm volatile("cp.async.wait_group 0;" ::: "memory")
#define CP_WAIT1()  asm volatile("cp.async.wait_group 1;" ::: "memory")

#define LDSM_X4(r0, r1, r2, r3, addr)                                          \
    asm volatile("ldmatrix.sync.aligned.m8n8.x4.shared.b16 {%0,%1,%2,%3},[%4];"\
                 : "=r"(r0), "=r"(r1), "=r"(r2), "=r"(r3) : "r"(addr))
#define LDSM_X2(r0, r1, addr)                                                  \
    asm volatile("ldmatrix.sync.aligned.m8n8.x2.shared.b16 {%0,%1},[%2];"      \
                 : "=r"(r0), "=r"(r1) : "r"(addr))

__device__ __forceinline__ void mma_bf16(float* c,
                                         uint32_t a0, uint32_t a1, uint32_t a2, uint32_t a3,
                                         uint32_t b0, uint32_t b1) {
    asm volatile(
        "mma.sync.aligned.m16n8k16.row.col.f32.bf16.bf16.f32 "
        "{%0,%1,%2,%3},{%4,%5,%6,%7},{%8,%9},{%0,%1,%2,%3};"
        : "+f"(c[0]), "+f"(c[1]), "+f"(c[2]), "+f"(c[3])
        : "r"(a0), "r"(a1), "r"(a2), "r"(a3), "r"(b0), "r"(b1));
}

// ============================================================================
// Kernel 1: gather + FM; emits dnn_in as bf16 hi/lo (one warp per sample)
// ============================================================================
__global__ void gather_fm_kernel(const float* __restrict__ cont,
                                 const int*   __restrict__ cat,
                                 const float* __restrict__ w_cont,
                                 const float* __restrict__ b_cont,
                                 const float* __restrict__ t_first,
                                 const float* __restrict__ t_emb) {
    int warp = (blockIdx.x * blockDim.x + threadIdx.x) >> 5;
    int lane = threadIdx.x & 31;
    if (warp >= B_) return;
    const int b = warp;

    float v[16];
    #pragma unroll
    for (int i = 0; i < 16; i++) v[i] = 0.f;
    float q = 0.f, scal = 0.f;

    if (lane < F_) {
        int idx = cat[b * F_ + lane];
        const float4* row =
            reinterpret_cast<const float4*>(t_emb + ((size_t)lane * V_ + (size_t)idx) * E_);
        float4 r0 = row[0], r1 = row[1], r2 = row[2], r3 = row[3];
        v[0]=r0.x; v[1]=r0.y; v[2]=r0.z; v[3]=r0.w;
        v[4]=r1.x; v[5]=r1.y; v[6]=r1.z; v[7]=r1.w;
        v[8]=r2.x; v[9]=r2.y; v[10]=r2.z; v[11]=r2.w;
        v[12]=r3.x; v[13]=r3.y; v[14]=r3.z; v[15]=r3.w;

        size_t base = (size_t)b * LDA1_ + CONT_ + lane * E_;
        #pragma unroll
        for (int i = 0; i < 16; i++) {
            __nv_bfloat16 h = __float2bfloat16(v[i]);
            g_dnnh[base + i] = h;
            g_dnnl[base + i] = __float2bfloat16(v[i] - __bfloat162float(h));
            q = fmaf(v[i], v[i], q);
        }
        scal = t_first[(size_t)lane * V_ + (size_t)idx];
    }
    if (lane < CONT_) {
        float c = cont[b * CONT_ + lane];
        __nv_bfloat16 h = __float2bfloat16(c);
        g_dnnh[(size_t)b * LDA1_ + lane] = h;
        g_dnnl[(size_t)b * LDA1_ + lane] = __float2bfloat16(c - __bfloat162float(h));
        scal = fmaf(c, w_cont[lane], scal);
    }
    if (lane < LDA1_ - K1_) {   // zero pad cols 429..447
        g_dnnh[(size_t)b * LDA1_ + K1_ + lane] = __float2bfloat16(0.f);
        g_dnnl[(size_t)b * LDA1_ + K1_ + lane] = __float2bfloat16(0.f);
    }

    #pragma unroll
    for (int off = 16; off; off >>= 1) {
        #pragma unroll
        for (int e = 0; e < 16; e++)
            v[e] += __shfl_xor_sync(0xffffffffu, v[e], off);
        q    += __shfl_xor_sync(0xffffffffu, q,    off);
        scal += __shfl_xor_sync(0xffffffffu, scal, off);
    }
    if (lane == 0) {
        float ss = 0.f;
        #pragma unroll
        for (int e = 0; e < 16; e++) ss = fmaf(v[e], v[e], ss);
        g_fm[b] = scal + b_cont[0] + 0.5f * (ss - q);
    }
}

// ============================================================================
// Prep: transpose + pad weights into bf16 hi/lo K-major buffers
// ============================================================================
__global__ void prep_kernel(const float* __restrict__ W1, const float* __restrict__ W2) {
    int idx = blockIdx.x * blockDim.x + threadIdx.x;
    if (idx < NPAD_ * LDA1_) {               // W1T: [512][448]
        int n = idx / LDA1_, k = idx % LDA1_;
        float v = (n < H_ && k < K1_) ? W1[(size_t)k * H_ + n] : 0.f;
        __nv_bfloat16 h = __float2bfloat16(v);
        g_w1th[idx] = h;
        g_w1tl[idx] = __float2bfloat16(v - __bfloat162float(h));
    }
    if (idx < NPAD_ * K2PAD_) {              // W2T: [512][416]
        int n = idx / K2PAD_, k = idx % K2PAD_;
        float v = (n < H_ && k < H_) ? W2[(size_t)k * H_ + n] : 0.f;
        __nv_bfloat16 h = __float2bfloat16(v);
        g_w2th[idx] = h;
        g_w2tl[idx] = __float2bfloat16(v - __bfloat162float(h));
    }
}

// ============================================================================
// bf16x3 GEMM via legacy mma.sync m16n8k16.
//   C[128/CTA, 128/CTA] = A[.,K] @ W[N,K]^T ; BK=32; 256 thr; warp tile 64x32.
//   SMEM tiles padded to 80B rows -> conflict-free ldmatrix.
//   FUSE=0: relu(+bias) -> Ch/Cl hi/lo.  FUSE=1: fused dot with Wout -> g_part.
// ============================================================================
#define OFF_AH 0
#define OFF_AL 10240
#define OFF_BH 20480
#define OFF_BL 30720
#define STAGE_ 40960

template<bool FUSE>
__global__ void __launch_bounds__(256, 1)
gemm_bf16x3(const __nv_bfloat16* __restrict__ Ah, const __nv_bfloat16* __restrict__ Al,
            const __nv_bfloat16* __restrict__ Bh, const __nv_bfloat16* __restrict__ Bl,
            int ldk,                           // A row stride == W row stride (=K padded)
            const float* __restrict__ bias,    // [H_]
            const float* __restrict__ Wout,    // [1+H_] (FUSE)
            __nv_bfloat16* __restrict__ Ch, __nv_bfloat16* __restrict__ Cl, // (!FUSE)
            int ldc, int NKB) {
    extern __shared__ char smem_raw[];
    __shared__ float part[4][128];
    const uint32_t sbase = smem_u32(smem_raw);

    const int tid  = threadIdx.x;
    const int warp = tid >> 5, lane = tid & 31;
    const int gr = lane >> 2, gc = lane & 3;
    const int wm = (warp >> 2) * 64;
    const int wn = (warp & 3) * 32;
    const int m0 = blockIdx.y * 128;
    const int n0 = blockIdx.x * 128;

    const int lane8 = lane & 7;
    const int laneH = (lane >> 3) & 1;
    const int laneK = lane >> 4;
    // ldmatrix per-lane byte offsets within tile (row stride 80B)
    const uint32_t aoff = (uint32_t)((wm + lane8 + laneH * 8) * 80 + laneK * 16);
    const uint32_t boff = (uint32_t)((wn + lane8) * 80 + laneH * 16);

    float acc[4][4][4];
    #pragma unroll
    for (int i = 0; i < 4; i++)
        #pragma unroll
        for (int j = 0; j < 4; j++)
            #pragma unroll
            for (int k = 0; k < 4; k++) acc[i][j][k] = 0.f;

    // ---- tile loader: 8 cp.async of 16B per thread ----
    #define LOAD_KB(KB, BUF)                                                          \
    do {                                                                              \
        const int k0_ = (KB) * 32;                                                    \
        const uint32_t st_ = sbase + (BUF) * STAGE_;                                  \
        _Pragma("unroll")                                                             \
        for (int h = 0; h < 2; h++) {                                                 \
            int c_ = tid + h * 256;                                                   \
            int row_ = c_ >> 2, q_ = c_ & 3;                                          \
            uint32_t d_ = st_ + row_ * 80 + q_ * 16;                                  \
            const __nv_bfloat16* sa_ = Ah + (size_t)(m0 + row_) * ldk + k0_ + q_ * 8; \
            const __nv_bfloat16* sl_ = Al + (size_t)(m0 + row_) * ldk + k0_ + q_ * 8; \
            const __nv_bfloat16* sb_ = Bh + (size_t)(n0 + row_) * ldk + k0_ + q_ * 8; \
            const __nv_bfloat16* sc_ = Bl + (size_t)(n0 + row_) * ldk + k0_ + q_ * 8; \
            CP16(d_ + OFF_AH, sa_);                                                   \
            CP16(d_ + OFF_AL, sl_);                                                   \
            CP16(d_ + OFF_BH, sb_);                                                   \
            CP16(d_ + OFF_BL, sc_);                                                   \
        }                                                                             \
    } while (0)

    LOAD_KB(0, 0);
    CP_COMMIT();

    for (int kb = 0; kb < NKB; kb++) {
        const int buf = kb & 1;
        if (kb + 1 < NKB) { LOAD_KB(kb + 1, buf ^ 1); CP_COMMIT(); CP_WAIT1(); }
        else              { CP_WAIT0(); }
        __syncthreads();

        const uint32_t st = sbase + buf * STAGE_;
        #pragma unroll
        for (int ks = 0; ks < 2; ks++) {
            const uint32_t ko = ks * 32;   // 16 bf16 = 32B
            uint32_t ah[4][4], al[4][4], bh[4][2], bl[4][2];
            #pragma unroll
            for (int mi = 0; mi < 4; mi++) {
                uint32_t ad = st + aoff + mi * 1280 + ko;
                LDSM_X4(ah[mi][0], ah[mi][1], ah[mi][2], ah[mi][3], ad + OFF_AH);
                LDSM_X4(al[mi][0], al[mi][1], al[mi][2], al[mi][3], ad + OFF_AL);
            }
            #pragma unroll
            for (int ni = 0; ni < 4; ni++) {
                uint32_t bd = st + boff + ni * 640 + ko;
                LDSM_X2(bh[ni][0], bh[ni][1], bd + OFF_BH);
                LDSM_X2(bl[ni][0], bl[ni][1], bd + OFF_BL);
            }
            #pragma unroll
            for (int mi = 0; mi < 4; mi++)
                #pragma unroll
                for (int ni = 0; ni < 4; ni++) {
                    mma_bf16(acc[mi][ni], ah[mi][0], ah[mi][1], ah[mi][2], ah[mi][3],
                             bh[ni][0], bh[ni][1]);
                    mma_bf16(acc[mi][ni], al[mi][0], al[mi][1], al[mi][2], al[mi][3],
                             bh[ni][0], bh[ni][1]);
                    mma_bf16(acc[mi][ni], ah[mi][0], ah[mi][1], ah[mi][2], ah[mi][3],
                             bl[ni][0], bl[ni][1]);
                }
        }
        __syncthreads();
    }
    #undef LOAD_KB

    // ---- epilogue ----
    if (!FUSE) {
        #pragma unroll
        for (int mi = 0; mi < 4; mi++) {
            int r = m0 + wm + mi * 16 + gr;
            #pragma unroll
            for (int ni = 0; ni < 4; ni++) {
                int n = n0 + wn + ni * 8 + gc * 2;
                if (n < K2PAD_) {
                    float b0v = (n     < H_) ? bias[n]     : 0.f;
                    float b1v = (n + 1 < H_) ? bias[n + 1] : 0.f;
                    #pragma unroll
                    for (int half = 0; half < 2; half++) {
                        float x0 = fmaxf(acc[mi][ni][half * 2 + 0] + b0v, 0.f);
                        float x1 = fmaxf(acc[mi][ni][half * 2 + 1] + b1v, 0.f);
                        __nv_bfloat16 h0 = __float2bfloat16(x0);
                        __nv_bfloat16 h1 = __float2bfloat16(x1);
                        __nv_bfloat16 l0 = __float2bfloat16(x0 - __bfloat162float(h0));
                        __nv_bfloat16 l1 = __float2bfloat16(x1 - __bfloat162float(h1));
                        uint32_t ph = (uint32_t)__bfloat16_as_ushort(h0) |
                                      ((uint32_t)__bfloat16_as_ushort(h1) << 16);
                        uint32_t pl = (uint32_t)__bfloat16_as_ushort(l0) |
                                      ((uint32_t)__bfloat16_as_ushort(l1) << 16);
                        size_t o = (size_t)(r + half * 8) * ldc + n;
                        *reinterpret_cast<uint32_t*>(Ch + o) = ph;
                        *reinterpret_cast<uint32_t*>(Cl + o) = pl;
                    }
                }
            }
        }
    } else {
        #pragma unroll
        for (int mi = 0; mi < 4; mi++) {
            float s0 = 0.f, s1 = 0.f;
            #pragma unroll
            for (int ni = 0; ni < 4; ni++) {
                int n = n0 + wn + ni * 8 + gc * 2;
                float w0v = 0.f, w1v = 0.f, b0v = 0.f, b1v = 0.f;
                if (n < H_)     { w0v = Wout[1 + n]; b0v = bias[n]; }
                if (n + 1 < H_) { w1v = Wout[2 + n]; b1v = bias[n + 1]; }
                s0 = fmaf(fmaxf(acc[mi][ni][0] + b0v, 0.f), w0v, s0);
                s0 = fmaf(fmaxf(acc[mi][ni][1] + b1v, 0.f), w1v, s0);
                s1 = fmaf(fmaxf(acc[mi][ni][2] + b0v, 0.f), w0v, s1);
                s1 = fmaf(fmaxf(acc[mi][ni][3] + b1v, 0.f), w1v, s1);
            }
            s0 += __shfl_xor_sync(0xffffffffu, s0, 1);
            s0 += __shfl_xor_sync(0xffffffffu, s0, 2);
            s1 += __shfl_xor_sync(0xffffffffu, s1, 1);
            s1 += __shfl_xor_sync(0xffffffffu, s1, 2);
            if (gc == 0) {
                part[warp & 3][wm + mi * 16 + gr]     = s0;
                part[warp & 3][wm + mi * 16 + gr + 8] = s1;
            }
        }
        __syncthreads();
        if (tid < 128) {
            float t = part[0][tid] + part[1][tid] + part[2][tid] + part[3][tid];
            g_part[blockIdx.x][m0 + tid] = t;
        }
    }
}

// ============================================================================
// Finish: out[b] = fm[b]*Wout[0] + b_out + sum_p g_part[p][b]
// ============================================================================
__global__ void finish_kernel(const float* __restrict__ Wout,
                              const float* __restrict__ bout,
                              float* __restrict__ out) {
    int b = blockIdx.x * blockDim.x + threadIdx.x;
    if (b >= B_) return;
    float s = g_part[0][b] + g_part[1][b] + g_part[2][b] + g_part[3][b];
    out[b] = fmaf(g_fm[b], Wout[0], bout[0] + s);
}

// ============================================================================
// Launch
// ============================================================================
static void* sym_addr(const void* symbol) {
    void* p = nullptr;
    cudaGetSymbolAddress(&p, symbol);
    return p;
}

extern "C" void kernel_launch(void* const* d_in, const int* in_sizes, int n_in,
                              void* d_out, int out_size) {
    const float* cont    = (const float*)d_in[0];
    const int*   cat     = (const int*)  d_in[1];
    const float* w_cont  = (const float*)d_in[2];
    const float* b_cont  = (const float*)d_in[3];
    const float* t_first = (const float*)d_in[4];
    const float* t_emb   = (const float*)d_in[5];
    const float* W1      = (const float*)d_in[6];
    const float* b1      = (const float*)d_in[7];
    const float* W2      = (const float*)d_in[8];
    const float* b2      = (const float*)d_in[9];
    const float* Wout    = (const float*)d_in[10];
    const float* bout    = (const float*)d_in[11];
    float* out = (float*)d_out;

    const int SMEM_DYN = 2 * STAGE_;
    cudaFuncSetAttribute(gemm_bf16x3<false>, cudaFuncAttributeMaxDynamicSharedMemorySize, SMEM_DYN);
    cudaFuncSetAttribute(gemm_bf16x3<true>,  cudaFuncAttributeMaxDynamicSharedMemorySize, SMEM_DYN);

    __nv_bfloat16* dnnh = (__nv_bfloat16*)sym_addr(g_dnnh);
    __nv_bfloat16* dnnl = (__nv_bfloat16*)sym_addr(g_dnnl);
    __nv_bfloat16* h1h  = (__nv_bfloat16*)sym_addr(g_h1h);
    __nv_bfloat16* h1l  = (__nv_bfloat16*)sym_addr(g_h1l);
    __nv_bfloat16* w1th = (__nv_bfloat16*)sym_addr(g_w1th);
    __nv_bfloat16* w1tl = (__nv_bfloat16*)sym_addr(g_w1tl);
    __nv_bfloat16* w2th = (__nv_bfloat16*)sym_addr(g_w2th);
    __nv_bfloat16* w2tl = (__nv_bfloat16*)sym_addr(g_w2tl);

    // 1) weight prep (transpose + pad + bf16 hi/lo split)
    prep_kernel<<<(NPAD_ * LDA1_ + 255) / 256, 256>>>(W1, W2);

    // 2) gather + FM + dnn_in (bf16 hi/lo)
    gather_fm_kernel<<<B_ / 8, 256>>>(cont, cat, w_cont, b_cont, t_first, t_emb);

    // 3) h1 = relu(dnn_in @ W1 + b1)
    dim3 grid(4, B_ / 128);
    gemm_bf16x3<false><<<grid, 256, SMEM_DYN>>>(dnnh, dnnl, w1th, w1tl, LDA1_,
                                                b1, nullptr, h1h, h1l, K2PAD_, LDA1_ / 32);

    // 4) fused: h2 = relu(h1 @ W2 + b2); g_part = per-tile dot(h2, Wout[1:])
    gemm_bf16x3<true><<<grid, 256, SMEM_DYN>>>(h1h, h1l, w2th, w2tl, K2PAD_,
                                               b2, Wout, nullptr, nullptr, 0, K2PAD_ / 32);

    // 5) out = fm*Wout[0] + b_out + parts
    finish_kernel<<<B_ / 256, 256>>>(Wout, bout, out);
}

// round 5
// speedup vs baseline: 2.3064x; 1.0002x over previous
#include <cuda_runtime.h>
#include <cuda_bf16.h>
#include <cstdint>

// ---------------- Problem constants ----------------
#define B_     16384
#define F_     26
#define V_     100000
#define E_     16
#define CONT_  13
#define K1_    429     // CONT_ + F_*E_
#define LDA1_  448     // K1_ padded to multiple of 32
#define K2PAD_ 416     // H_(400) padded to multiple of 32
#define NPAD_  512     // H_ padded to multiple of 128 (weight rows)
#define H_     400

// ---------------- Scratch (device globals) ----------------
__device__ __align__(256) __nv_bfloat16 g_dnnh[(size_t)B_ * LDA1_];
__device__ __align__(256) __nv_bfloat16 g_dnnl[(size_t)B_ * LDA1_];
__device__ __align__(256) __nv_bfloat16 g_h1h [(size_t)B_ * K2PAD_];
__device__ __align__(256) __nv_bfloat16 g_h1l [(size_t)B_ * K2PAD_];
__device__ __align__(256) __nv_bfloat16 g_w1th[(size_t)NPAD_ * LDA1_];   // [n][k] = W1[k][n]
__device__ __align__(256) __nv_bfloat16 g_w1tl[(size_t)NPAD_ * LDA1_];
__device__ __align__(256) __nv_bfloat16 g_w2th[(size_t)NPAD_ * K2PAD_];  // [n][k] = W2[k][n]
__device__ __align__(256) __nv_bfloat16 g_w2tl[(size_t)NPAD_ * K2PAD_];
__device__ float g_fm  [B_];
__device__ float g_part[4][B_];

// ---------------- PTX helpers ----------------
__device__ __forceinline__ uint32_t smem_u32(const void* p) {
    return (uint32_t)__cvta_generic_to_shared(p);
}
#define CP16(dst_u32, src) \
    asm volatile("cp.async.cg.shared.global [%0], [%1], 16;" :: "r"(dst_u32), "l"(src))
#define CP_COMMIT() asm volatile("cp.async.commit_group;" ::: "memory")
#define CP_WAIT0()  asm volatile("cp.async.wait_group 0;" ::: "memory")
#define CP_WAIT1()  asm volatile("cp.async.wait_group 1;" ::: "memory")

#define LDSM_X4(r0, r1, r2, r3, addr)                                          \
    asm volatile("ldmatrix.sync.aligned.m8n8.x4.shared.b16 {%0,%1,%2,%3},[%4];"\
                 : "=r"(r0), "=r"(r1), "=r"(r2), "=r"(r3) : "r"(addr))

__device__ __forceinline__ void mma_bf16(float* c,
                                         uint32_t a0, uint32_t a1, uint32_t a2, uint32_t a3,
                                         uint32_t b0, uint32_t b1) {
    asm volatile(
        "mma.sync.aligned.m16n8k16.row.col.f32.bf16.bf16.f32 "
        "{%0,%1,%2,%3},{%4,%5,%6,%7},{%8,%9},{%0,%1,%2,%3};"
        : "+f"(c[0]), "+f"(c[1]), "+f"(c[2]), "+f"(c[3])
        : "r"(a0), "r"(a1), "r"(a2), "r"(a3), "r"(b0), "r"(b1));
}

// ============================================================================
// Kernel 1: gather + FM; emits dnn_in as bf16 hi/lo (one warp per sample)
// ============================================================================
__global__ void gather_fm_kernel(const float* __restrict__ cont,
                                 const int*   __restrict__ cat,
                                 const float* __restrict__ w_cont,
                                 const float* __restrict__ b_cont,
                                 const float* __restrict__ t_first,
                                 const float* __restrict__ t_emb) {
    int warp = (blockIdx.x * blockDim.x + threadIdx.x) >> 5;
    int lane = threadIdx.x & 31;
    if (warp >= B_) return;
    const int b = warp;

    float v[16];
    #pragma unroll
    for (int i = 0; i < 16; i++) v[i] = 0.f;
    float q = 0.f, scal = 0.f;

    if (lane < F_) {
        int idx = cat[b * F_ + lane];
        const float4* row =
            reinterpret_cast<const float4*>(t_emb + ((size_t)lane * V_ + (size_t)idx) * E_);
        float4 r0 = row[0], r1 = row[1], r2 = row[2], r3 = row[3];
        v[0]=r0.x; v[1]=r0.y; v[2]=r0.z; v[3]=r0.w;
        v[4]=r1.x; v[5]=r1.y; v[6]=r1.z; v[7]=r1.w;
        v[8]=r2.x; v[9]=r2.y; v[10]=r2.z; v[11]=r2.w;
        v[12]=r3.x; v[13]=r3.y; v[14]=r3.z; v[15]=r3.w;

        size_t base = (size_t)b * LDA1_ + CONT_ + lane * E_;
        #pragma unroll
        for (int i = 0; i < 16; i++) {
            __nv_bfloat16 h = __float2bfloat16(v[i]);
            g_dnnh[base + i] = h;
            g_dnnl[base + i] = __float2bfloat16(v[i] - __bfloat162float(h));
            q = fmaf(v[i], v[i], q);
        }
        scal = t_first[(size_t)lane * V_ + (size_t)idx];
    }
    if (lane < CONT_) {
        float c = cont[b * CONT_ + lane];
        __nv_bfloat16 h = __float2bfloat16(c);
        g_dnnh[(size_t)b * LDA1_ + lane] = h;
        g_dnnl[(size_t)b * LDA1_ + lane] = __float2bfloat16(c - __bfloat162float(h));
        scal = fmaf(c, w_cont[lane], scal);
    }
    if (lane < LDA1_ - K1_) {   // zero pad cols 429..447
        g_dnnh[(size_t)b * LDA1_ + K1_ + lane] = __float2bfloat16(0.f);
        g_dnnl[(size_t)b * LDA1_ + K1_ + lane] = __float2bfloat16(0.f);
    }

    #pragma unroll
    for (int off = 16; off; off >>= 1) {
        #pragma unroll
        for (int e = 0; e < 16; e++)
            v[e] += __shfl_xor_sync(0xffffffffu, v[e], off);
        q    += __shfl_xor_sync(0xffffffffu, q,    off);
        scal += __shfl_xor_sync(0xffffffffu, scal, off);
    }
    if (lane == 0) {
        float ss = 0.f;
        #pragma unroll
        for (int e = 0; e < 16; e++) ss = fmaf(v[e], v[e], ss);
        g_fm[b] = scal + b_cont[0] + 0.5f * (ss - q);
    }
}

// ============================================================================
// Prep: transpose + pad weights into bf16 hi/lo K-major buffers
// ============================================================================
__global__ void prep_kernel(const float* __restrict__ W1, const float* __restrict__ W2) {
    int idx = blockIdx.x * blockDim.x + threadIdx.x;
    if (idx < NPAD_ * LDA1_) {               // W1T: [512][448]
        int n = idx / LDA1_, k = idx % LDA1_;
        float v = (n < H_ && k < K1_) ? W1[(size_t)k * H_ + n] : 0.f;
        __nv_bfloat16 h = __float2bfloat16(v);
        g_w1th[idx] = h;
        g_w1tl[idx] = __float2bfloat16(v - __bfloat162float(h));
    }
    if (idx < NPAD_ * K2PAD_) {              // W2T: [512][416]
        int n = idx / K2PAD_, k = idx % K2PAD_;
        float v = (n < H_ && k < H_) ? W2[(size_t)k * H_ + n] : 0.f;
        __nv_bfloat16 h = __float2bfloat16(v);
        g_w2th[idx] = h;
        g_w2tl[idx] = __float2bfloat16(v - __bfloat162float(h));
    }
}

// ============================================================================
// bf16x3 GEMM via mma.sync m16n8k16, 512 threads, 16 warps, warp tile 32x32.
//   CTA tile 128x128, BK=32, double-buffered cp.async.
//   SMEM rows padded to 80B -> conflict-free ldmatrix.
//   FUSE=0: relu(+bias) -> Ch/Cl hi/lo.  FUSE=1: fused dot with Wout -> g_part.
// ============================================================================
#define OFF_AH 0
#define OFF_AL 10240
#define OFF_BH 20480
#define OFF_BL 30720
#define STAGE_ 40960

template<bool FUSE>
__global__ void __launch_bounds__(512, 1)
gemm_bf16x3(const __nv_bfloat16* __restrict__ Ah, const __nv_bfloat16* __restrict__ Al,
            const __nv_bfloat16* __restrict__ Bh, const __nv_bfloat16* __restrict__ Bl,
            int ldk,                           // K stride (padded)
            const float* __restrict__ bias,    // [H_]
            const float* __restrict__ Wout,    // [1+H_] (FUSE)
            __nv_bfloat16* __restrict__ Ch, __nv_bfloat16* __restrict__ Cl, // (!FUSE)
            int ldc, int NKB) {
    extern __shared__ char smem_raw[];
    __shared__ float part[4][128];
    const uint32_t sbase = smem_u32(smem_raw);

    const int tid  = threadIdx.x;
    const int warp = tid >> 5, lane = tid & 31;
    const int gr = lane >> 2, gc = lane & 3;
    const int wm = (warp >> 2) * 32;     // warp row band (0..96)
    const int wn = (warp & 3) * 32;      // warp col band (0..96)
    const int m0 = blockIdx.y * 128;
    const int n0 = blockIdx.x * 128;

    const int lane8 = lane & 7;
    const int laneH = (lane >> 3) & 1;
    const int laneK = lane >> 4;
    // A ldmatrix.x4 (16x16 tile): rows = wm+mi*16 + lane8 + laneH*8, k-half = laneK
    const uint32_t aoff  = (uint32_t)((wm + lane8 + laneH * 8) * 80 + laneK * 16);
    // B ldmatrix.x4 (two n8 x k16 frags): rows = wn+nj*16 + lane8 + laneK*8, k-half = laneH
    const uint32_t boff4 = (uint32_t)((wn + lane8 + laneK * 8) * 80 + laneH * 16);

    float acc[2][4][4];
    #pragma unroll
    for (int i = 0; i < 2; i++)
        #pragma unroll
        for (int j = 0; j < 4; j++)
            #pragma unroll
            for (int k = 0; k < 4; k++) acc[i][j][k] = 0.f;

    // ---- tile loader: exactly 1 chunk (16B) per thread per tile ----
    const int lrow = tid >> 2, lq = tid & 3;
    #define LOAD_KB(KB, BUF)                                                        \
    do {                                                                            \
        const int k0_ = (KB) * 32;                                                  \
        const uint32_t d_ = sbase + (BUF) * STAGE_ + lrow * 80 + lq * 16;           \
        CP16(d_ + OFF_AH, Ah + (size_t)(m0 + lrow) * ldk + k0_ + lq * 8);           \
        CP16(d_ + OFF_AL, Al + (size_t)(m0 + lrow) * ldk + k0_ + lq * 8);           \
        CP16(d_ + OFF_BH, Bh + (size_t)(n0 + lrow) * ldk + k0_ + lq * 8);           \
        CP16(d_ + OFF_BL, Bl + (size_t)(n0 + lrow) * ldk + k0_ + lq * 8);           \
    } while (0)

    LOAD_KB(0, 0);
    CP_COMMIT();

    for (int kb = 0; kb < NKB; kb++) {
        const int buf = kb & 1;
        if (kb + 1 < NKB) { LOAD_KB(kb + 1, buf ^ 1); CP_COMMIT(); CP_WAIT1(); }
        else              { CP_WAIT0(); }
        __syncthreads();

        const uint32_t st = sbase + buf * STAGE_;
        #pragma unroll
        for (int ks = 0; ks < 2; ks++) {
            const uint32_t ko = ks * 32;   // 16 bf16 = 32B
            uint32_t ah[2][4], al[2][4], bh[4][2], bl[4][2];
            #pragma unroll
            for (int mi = 0; mi < 2; mi++) {
                uint32_t ad = st + aoff + mi * 1280 + ko;
                LDSM_X4(ah[mi][0], ah[mi][1], ah[mi][2], ah[mi][3], ad + OFF_AH);
                LDSM_X4(al[mi][0], al[mi][1], al[mi][2], al[mi][3], ad + OFF_AL);
            }
            #pragma unroll
            for (int nj = 0; nj < 2; nj++) {
                uint32_t bd = st + boff4 + nj * 1280 + ko;
                LDSM_X4(bh[nj*2][0], bh[nj*2][1], bh[nj*2+1][0], bh[nj*2+1][1], bd + OFF_BH);
                LDSM_X4(bl[nj*2][0], bl[nj*2][1], bl[nj*2+1][0], bl[nj*2+1][1], bd + OFF_BL);
            }
            #pragma unroll
            for (int mi = 0; mi < 2; mi++)
                #pragma unroll
                for (int ni = 0; ni < 4; ni++) {
                    mma_bf16(acc[mi][ni], ah[mi][0], ah[mi][1], ah[mi][2], ah[mi][3],
                             bh[ni][0], bh[ni][1]);
                    mma_bf16(acc[mi][ni], al[mi][0], al[mi][1], al[mi][2], al[mi][3],
                             bh[ni][0], bh[ni][1]);
                    mma_bf16(acc[mi][ni], ah[mi][0], ah[mi][1], ah[mi][2], ah[mi][3],
                             bl[ni][0], bl[ni][1]);
                }
        }
        __syncthreads();
    }
    #undef LOAD_KB

    // ---- epilogue ----
    if (!FUSE) {
        #pragma unroll
        for (int mi = 0; mi < 2; mi++) {
            int r = m0 + wm + mi * 16 + gr;
            #pragma unroll
            for (int ni = 0; ni < 4; ni++) {
                int n = n0 + wn + ni * 8 + gc * 2;
                if (n < K2PAD_) {
                    float b0v = (n     < H_) ? bias[n]     : 0.f;
                    float b1v = (n + 1 < H_) ? bias[n + 1] : 0.f;
                    #pragma unroll
                    for (int half = 0; half < 2; half++) {
                        float x0 = fmaxf(acc[mi][ni][half * 2 + 0] + b0v, 0.f);
                        float x1 = fmaxf(acc[mi][ni][half * 2 + 1] + b1v, 0.f);
                        __nv_bfloat16 h0 = __float2bfloat16(x0);
                        __nv_bfloat16 h1 = __float2bfloat16(x1);
                        __nv_bfloat16 l0 = __float2bfloat16(x0 - __bfloat162float(h0));
                        __nv_bfloat16 l1 = __float2bfloat16(x1 - __bfloat162float(h1));
                        uint32_t ph = (uint32_t)__bfloat16_as_ushort(h0) |
                                      ((uint32_t)__bfloat16_as_ushort(h1) << 16);
                        uint32_t pl = (uint32_t)__bfloat16_as_ushort(l0) |
                                      ((uint32_t)__bfloat16_as_ushort(l1) << 16);
                        size_t o = (size_t)(r + half * 8) * ldc + n;
                        *reinterpret_cast<uint32_t*>(Ch + o) = ph;
                        *reinterpret_cast<uint32_t*>(Cl + o) = pl;
                    }
                }
            }
        }
    } else {
        #pragma unroll
        for (int mi = 0; mi < 2; mi++) {
            float s0 = 0.f, s1 = 0.f;
            #pragma unroll
            for (int ni = 0; ni < 4; ni++) {
                int n = n0 + wn + ni * 8 + gc * 2;
                float w0v = 0.f, w1v = 0.f, b0v = 0.f, b1v = 0.f;
                if (n < H_)     { w0v = Wout[1 + n]; b0v = bias[n]; }
                if (n + 1 < H_) { w1v = Wout[2 + n]; b1v = bias[n + 1]; }
                s0 = fmaf(fmaxf(acc[mi][ni][0] + b0v, 0.f), w0v, s0);
                s0 = fmaf(fmaxf(acc[mi][ni][1] + b1v, 0.f), w1v, s0);
                s1 = fmaf(fmaxf(acc[mi][ni][2] + b0v, 0.f), w0v, s1);
                s1 = fmaf(fmaxf(acc[mi][ni][3] + b1v, 0.f), w1v, s1);
            }
            s0 += __shfl_xor_sync(0xffffffffu, s0, 1);
            s0 += __shfl_xor_sync(0xffffffffu, s0, 2);
            s1 += __shfl_xor_sync(0xffffffffu, s1, 1);
            s1 += __shfl_xor_sync(0xffffffffu, s1, 2);
            if (gc == 0) {
                part[warp & 3][wm + mi * 16 + gr]     = s0;
                part[warp & 3][wm + mi * 16 + gr + 8] = s1;
            }
        }
        __syncthreads();
        if (tid < 128) {
            float t = part[0][tid] + part[1][tid] + part[2][tid] + part[3][tid];
            g_part[blockIdx.x][m0 + tid] = t;
        }
    }
}

// ============================================================================
// Finish: out[b] = fm[b]*Wout[0] + b_out + sum_p g_part[p][b]
// ============================================================================
__global__ void finish_kernel(const float* __restrict__ Wout,
                              const float* __restrict__ bout,
                              float* __restrict__ out) {
    int b = blockIdx.x * blockDim.x + threadIdx.x;
    if (b >= B_) return;
    float s = g_part[0][b] + g_part[1][b] + g_part[2][b] + g_part[3][b];
    out[b] = fmaf(g_fm[b], Wout[0], bout[0] + s);
}

// ============================================================================
// Launch
// ============================================================================
static void* sym_addr(const void* symbol) {
    void* p = nullptr;
    cudaGetSymbolAddress(&p, symbol);
    return p;
}

extern "C" void kernel_launch(void* const* d_in, const int* in_sizes, int n_in,
                              void* d_out, int out_size) {
    const float* cont    = (const float*)d_in[0];
    const int*   cat     = (const int*)  d_in[1];
    const float* w_cont  = (const float*)d_in[2];
    const float* b_cont  = (const float*)d_in[3];
    const float* t_first = (const float*)d_in[4];
    const float* t_emb   = (const float*)d_in[5];
    const float* W1      = (const float*)d_in[6];
    const float* b1      = (const float*)d_in[7];
    const float* W2      = (const float*)d_in[8];
    const float* b2      = (const float*)d_in[9];
    const float* Wout    = (const float*)d_in[10];
    const float* bout    = (const float*)d_in[11];
    float* out = (float*)d_out;

    const int SMEM_DYN = 2 * STAGE_;
    cudaFuncSetAttribute(gemm_bf16x3<false>, cudaFuncAttributeMaxDynamicSharedMemorySize, SMEM_DYN);
    cudaFuncSetAttribute(gemm_bf16x3<true>,  cudaFuncAttributeMaxDynamicSharedMemorySize, SMEM_DYN);

    __nv_bfloat16* dnnh = (__nv_bfloat16*)sym_addr(g_dnnh);
    __nv_bfloat16* dnnl = (__nv_bfloat16*)sym_addr(g_dnnl);
    __nv_bfloat16* h1h  = (__nv_bfloat16*)sym_addr(g_h1h);
    __nv_bfloat16* h1l  = (__nv_bfloat16*)sym_addr(g_h1l);
    __nv_bfloat16* w1th = (__nv_bfloat16*)sym_addr(g_w1th);
    __nv_bfloat16* w1tl = (__nv_bfloat16*)sym_addr(g_w1tl);
    __nv_bfloat16* w2th = (__nv_bfloat16*)sym_addr(g_w2th);
    __nv_bfloat16* w2tl = (__nv_bfloat16*)sym_addr(g_w2tl);

    // 1) weight prep (transpose + pad + bf16 hi/lo split)
    prep_kernel<<<(NPAD_ * LDA1_ + 255) / 256, 256>>>(W1, W2);

    // 2) gather + FM + dnn_in (bf16 hi/lo)
    gather_fm_kernel<<<B_ / 8, 256>>>(cont, cat, w_cont, b_cont, t_first, t_emb);

    // 3) h1 = relu(dnn_in @ W1 + b1)
    dim3 grid(4, B_ / 128);
    gemm_bf16x3<false><<<grid, 512, SMEM_DYN>>>(dnnh, dnnl, w1th, w1tl, LDA1_,
                                                b1, nullptr, h1h, h1l, K2PAD_, LDA1_ / 32);

    // 4) fused: h2 = relu(h1 @ W2 + b2); g_part = per-tile dot(h2, Wout[1:])
    gemm_bf16x3<true><<<grid, 512, SMEM_DYN>>>(h1h, h1l, w2th, w2tl, K2PAD_,
                                               b2, Wout, nullptr, nullptr, 0, K2PAD_ / 32);

    // 5) out = fm*Wout[0] + b_out + parts
    finish_kernel<<<B_ / 256, 256>>>(Wout, bout, out);
}

// round 6
// speedup vs baseline: 2.8641x; 1.2418x over previous
#include <cuda_runtime.h>
#include <cuda_bf16.h>
#include <cuda_fp16.h>
#include <cstdint>

// ---------------- Problem constants ----------------
#define B_     16384
#define F_     26
#define V_     100000
#define E_     16
#define CONT_  13
#define K1_    429     // CONT_ + F_*E_
#define LDA1_  448     // K1_ padded to multiple of 32
#define K2PAD_ 416     // H_(400) padded to multiple of 32
#define NPAD_  512     // H_ padded to multiple of 128 (weight rows)
#define H_     400

// ---------------- Scratch (device globals) ----------------
__device__ __align__(256) __half g_dnnh[(size_t)B_ * LDA1_];
__device__ __align__(256) __half g_dnnl[(size_t)B_ * LDA1_];
__device__ __align__(256) __half g_h1h [(size_t)B_ * K2PAD_];
__device__ __align__(256) __half g_h1l [(size_t)B_ * K2PAD_];
__device__ __align__(256) __half g_w1t [(size_t)NPAD_ * LDA1_];   // [n][k] = fp16(W1[k][n])
__device__ __align__(256) __half g_w2t [(size_t)NPAD_ * K2PAD_];  // [n][k] = fp16(W2[k][n])
__device__ float g_fm  [B_];
__device__ float g_part[4][B_];

// ---------------- PTX helpers ----------------
__device__ __forceinline__ uint32_t smem_u32(const void* p) {
    return (uint32_t)__cvta_generic_to_shared(p);
}
#define CP16(dst_u32, src) \
    asm volatile("cp.async.cg.shared.global [%0], [%1], 16;" :: "r"(dst_u32), "l"(src))
#define CP_COMMIT() asm volatile("cp.async.commit_group;" ::: "memory")
#define CP_WAIT0()  asm volatile("cp.async.wait_group 0;" ::: "memory")
#define CP_WAIT1()  asm volatile("cp.async.wait_group 1;" ::: "memory")

#define LDSM_X4(r0, r1, r2, r3, addr)                                          \
    asm volatile("ldmatrix.sync.aligned.m8n8.x4.shared.b16 {%0,%1,%2,%3},[%4];"\
                 : "=r"(r0), "=r"(r1), "=r"(r2), "=r"(r3) : "r"(addr))

__device__ __forceinline__ void mma_fp16(float* c,
                                         uint32_t a0, uint32_t a1, uint32_t a2, uint32_t a3,
                                         uint32_t b0, uint32_t b1) {
    asm volatile(
        "mma.sync.aligned.m16n8k16.row.col.f32.f16.f16.f32 "
        "{%0,%1,%2,%3},{%4,%5,%6,%7},{%8,%9},{%0,%1,%2,%3};"
        : "+f"(c[0]), "+f"(c[1]), "+f"(c[2]), "+f"(c[3])
        : "r"(a0), "r"(a1), "r"(a2), "r"(a3), "r"(b0), "r"(b1));
}

__device__ __forceinline__ void split_fp16(float x, __half& h, __half& l) {
    h = __float2half_rn(x);
    l = __float2half_rn(x - __half2float(h));
}

// ============================================================================
// Kernel 1: gather + FM; emits dnn_in as fp16 hi/lo (one warp per sample)
// ============================================================================
__global__ void gather_fm_kernel(const float* __restrict__ cont,
                                 const int*   __restrict__ cat,
                                 const float* __restrict__ w_cont,
                                 const float* __restrict__ b_cont,
                                 const float* __restrict__ t_first,
                                 const float* __restrict__ t_emb) {
    int warp = (blockIdx.x * blockDim.x + threadIdx.x) >> 5;
    int lane = threadIdx.x & 31;
    if (warp >= B_) return;
    const int b = warp;

    float v[16];
    #pragma unroll
    for (int i = 0; i < 16; i++) v[i] = 0.f;
    float q = 0.f, scal = 0.f;

    if (lane < F_) {
        int idx = cat[b * F_ + lane];
        const float4* row =
            reinterpret_cast<const float4*>(t_emb + ((size_t)lane * V_ + (size_t)idx) * E_);
        float4 r0 = row[0], r1 = row[1], r2 = row[2], r3 = row[3];
        v[0]=r0.x; v[1]=r0.y; v[2]=r0.z; v[3]=r0.w;
        v[4]=r1.x; v[5]=r1.y; v[6]=r1.z; v[7]=r1.w;
        v[8]=r2.x; v[9]=r2.y; v[10]=r2.z; v[11]=r2.w;
        v[12]=r3.x; v[13]=r3.y; v[14]=r3.z; v[15]=r3.w;

        size_t base = (size_t)b * LDA1_ + CONT_ + lane * E_;
        #pragma unroll
        for (int i = 0; i < 16; i++) {
            __half h, l;
            split_fp16(v[i], h, l);
            g_dnnh[base + i] = h;
            g_dnnl[base + i] = l;
            q = fmaf(v[i], v[i], q);
        }
        scal = t_first[(size_t)lane * V_ + (size_t)idx];
    }
    if (lane < CONT_) {
        float c = cont[b * CONT_ + lane];
        __half h, l;
        split_fp16(c, h, l);
        g_dnnh[(size_t)b * LDA1_ + lane] = h;
        g_dnnl[(size_t)b * LDA1_ + lane] = l;
        scal = fmaf(c, w_cont[lane], scal);
    }
    if (lane < LDA1_ - K1_) {   // zero pad cols 429..447
        g_dnnh[(size_t)b * LDA1_ + K1_ + lane] = __float2half_rn(0.f);
        g_dnnl[(size_t)b * LDA1_ + K1_ + lane] = __float2half_rn(0.f);
    }

    #pragma unroll
    for (int off = 16; off; off >>= 1) {
        #pragma unroll
        for (int e = 0; e < 16; e++)
            v[e] += __shfl_xor_sync(0xffffffffu, v[e], off);
        q    += __shfl_xor_sync(0xffffffffu, q,    off);
        scal += __shfl_xor_sync(0xffffffffu, scal, off);
    }
    if (lane == 0) {
        float ss = 0.f;
        #pragma unroll
        for (int e = 0; e < 16; e++) ss = fmaf(v[e], v[e], ss);
        g_fm[b] = scal + b_cont[0] + 0.5f * (ss - q);
    }
}

// ============================================================================
// Prep: transpose + pad weights into fp16 K-major buffers (hi only)
// ============================================================================
__global__ void prep_kernel(const float* __restrict__ W1, const float* __restrict__ W2) {
    int idx = blockIdx.x * blockDim.x + threadIdx.x;
    if (idx < NPAD_ * LDA1_) {               // W1T: [512][448]
        int n = idx / LDA1_, k = idx % LDA1_;
        float v = (n < H_ && k < K1_) ? W1[(size_t)k * H_ + n] : 0.f;
        g_w1t[idx] = __float2half_rn(v);
    }
    if (idx < NPAD_ * K2PAD_) {              // W2T: [512][416]
        int n = idx / K2PAD_, k = idx % K2PAD_;
        float v = (n < H_ && k < H_) ? W2[(size_t)k * H_ + n] : 0.f;
        g_w2t[idx] = __float2half_rn(v);
    }
}

// ============================================================================
// fp16 2-term GEMM via mma.sync m16n8k16, 512 threads, warp tile 32x32.
//   C = (Ah + Al) @ Bh^T ; CTA tile 128x128, BK=32, double-buffered cp.async.
//   SMEM rows padded to 80B -> conflict-free ldmatrix.
//   FUSE=0: relu(+bias) -> Ch/Cl fp16 hi/lo.  FUSE=1: fused dot w/ Wout -> g_part.
// ============================================================================
#define OFF_AH 0
#define OFF_AL 10240
#define OFF_BH 20480
#define STAGE_ 30720

template<bool FUSE>
__global__ void __launch_bounds__(512, 1)
gemm_fp16x2(const __half* __restrict__ Ah, const __half* __restrict__ Al,
            const __half* __restrict__ Bh,
            int ldk,                           // K stride (padded)
            const float* __restrict__ bias,    // [H_]
            const float* __restrict__ Wout,    // [1+H_] (FUSE)
            __half* __restrict__ Ch, __half* __restrict__ Cl, // (!FUSE)
            int ldc, int NKB) {
    extern __shared__ char smem_raw[];
    __shared__ float part[4][128];
    const uint32_t sbase = smem_u32(smem_raw);

    const int tid  = threadIdx.x;
    const int warp = tid >> 5, lane = tid & 31;
    const int gr = lane >> 2, gc = lane & 3;
    const int wm = (warp >> 2) * 32;     // warp row band (0..96)
    const int wn = (warp & 3) * 32;      // warp col band (0..96)
    const int m0 = blockIdx.y * 128;
    const int n0 = blockIdx.x * 128;

    const int lane8 = lane & 7;
    const int laneH = (lane >> 3) & 1;
    const int laneK = lane >> 4;
    const uint32_t aoff  = (uint32_t)((wm + lane8 + laneH * 8) * 80 + laneK * 16);
    const uint32_t boff4 = (uint32_t)((wn + lane8 + laneK * 8) * 80 + laneH * 16);

    float acc[2][4][4];
    #pragma unroll
    for (int i = 0; i < 2; i++)
        #pragma unroll
        for (int j = 0; j < 4; j++)
            #pragma unroll
            for (int k = 0; k < 4; k++) acc[i][j][k] = 0.f;

    // ---- tile loader: 3 x 16B per thread per tile ----
    const int lrow = tid >> 2, lq = tid & 3;
    #define LOAD_KB(KB, BUF)                                                        \
    do {                                                                            \
        const int k0_ = (KB) * 32;                                                  \
        const uint32_t d_ = sbase + (BUF) * STAGE_ + lrow * 80 + lq * 16;           \
        CP16(d_ + OFF_AH, Ah + (size_t)(m0 + lrow) * ldk + k0_ + lq * 8);           \
        CP16(d_ + OFF_AL, Al + (size_t)(m0 + lrow) * ldk + k0_ + lq * 8);           \
        CP16(d_ + OFF_BH, Bh + (size_t)(n0 + lrow) * ldk + k0_ + lq * 8);           \
    } while (0)

    LOAD_KB(0, 0);
    CP_COMMIT();

    for (int kb = 0; kb < NKB; kb++) {
        const int buf = kb & 1;
        if (kb + 1 < NKB) { LOAD_KB(kb + 1, buf ^ 1); CP_COMMIT(); CP_WAIT1(); }
        else              { CP_WAIT0(); }
        __syncthreads();

        const uint32_t st = sbase + buf * STAGE_;
        #pragma unroll
        for (int ks = 0; ks < 2; ks++) {
            const uint32_t ko = ks * 32;   // 16 fp16 = 32B
            uint32_t ah[2][4], al[2][4], bh[4][2];
            #pragma unroll
            for (int mi = 0; mi < 2; mi++) {
                uint32_t ad = st + aoff + mi * 1280 + ko;
                LDSM_X4(ah[mi][0], ah[mi][1], ah[mi][2], ah[mi][3], ad + OFF_AH);
                LDSM_X4(al[mi][0], al[mi][1], al[mi][2], al[mi][3], ad + OFF_AL);
            }
            #pragma unroll
            for (int nj = 0; nj < 2; nj++) {
                uint32_t bd = st + boff4 + nj * 1280 + ko;
                LDSM_X4(bh[nj*2][0], bh[nj*2][1], bh[nj*2+1][0], bh[nj*2+1][1], bd + OFF_BH);
            }
            #pragma unroll
            for (int mi = 0; mi < 2; mi++)
                #pragma unroll
                for (int ni = 0; ni < 4; ni++) {
                    mma_fp16(acc[mi][ni], ah[mi][0], ah[mi][1], ah[mi][2], ah[mi][3],
                             bh[ni][0], bh[ni][1]);
                    mma_fp16(acc[mi][ni], al[mi][0], al[mi][1], al[mi][2], al[mi][3],
                             bh[ni][0], bh[ni][1]);
                }
        }
        __syncthreads();
    }
    #undef LOAD_KB

    // ---- epilogue ----
    if (!FUSE) {
        #pragma unroll
        for (int mi = 0; mi < 2; mi++) {
            int r = m0 + wm + mi * 16 + gr;
            #pragma unroll
            for (int ni = 0; ni < 4; ni++) {
                int n = n0 + wn + ni * 8 + gc * 2;
                if (n < K2PAD_) {
                    float b0v = (n     < H_) ? bias[n]     : 0.f;
                    float b1v = (n + 1 < H_) ? bias[n + 1] : 0.f;
                    #pragma unroll
                    for (int half = 0; half < 2; half++) {
                        float x0 = fmaxf(acc[mi][ni][half * 2 + 0] + b0v, 0.f);
                        float x1 = fmaxf(acc[mi][ni][half * 2 + 1] + b1v, 0.f);
                        __half h0, l0, h1, l1;
                        split_fp16(x0, h0, l0);
                        split_fp16(x1, h1, l1);
                        uint32_t ph = (uint32_t)__half_as_ushort(h0) |
                                      ((uint32_t)__half_as_ushort(h1) << 16);
                        uint32_t pl = (uint32_t)__half_as_ushort(l0) |
                                      ((uint32_t)__half_as_ushort(l1) << 16);
                        size_t o = (size_t)(r + half * 8) * ldc + n;
                        *reinterpret_cast<uint32_t*>(Ch + o) = ph;
                        *reinterpret_cast<uint32_t*>(Cl + o) = pl;
                    }
                }
            }
        }
    } else {
        #pragma unroll
        for (int mi = 0; mi < 2; mi++) {
            float s0 = 0.f, s1 = 0.f;
            #pragma unroll
            for (int ni = 0; ni < 4; ni++) {
                int n = n0 + wn + ni * 8 + gc * 2;
                float w0v = 0.f, w1v = 0.f, b0v = 0.f, b1v = 0.f;
                if (n < H_)     { w0v = Wout[1 + n]; b0v = bias[n]; }
                if (n + 1 < H_) { w1v = Wout[2 + n]; b1v = bias[n + 1]; }
                s0 = fmaf(fmaxf(acc[mi][ni][0] + b0v, 0.f), w0v, s0);
                s0 = fmaf(fmaxf(acc[mi][ni][1] + b1v, 0.f), w1v, s0);
                s1 = fmaf(fmaxf(acc[mi][ni][2] + b0v, 0.f), w0v, s1);
                s1 = fmaf(fmaxf(acc[mi][ni][3] + b1v, 0.f), w1v, s1);
            }
            s0 += __shfl_xor_sync(0xffffffffu, s0, 1);
            s0 += __shfl_xor_sync(0xffffffffu, s0, 2);
            s1 += __shfl_xor_sync(0xffffffffu, s1, 1);
            s1 += __shfl_xor_sync(0xffffffffu, s1, 2);
            if (gc == 0) {
                part[warp & 3][wm + mi * 16 + gr]     = s0;
                part[warp & 3][wm + mi * 16 + gr + 8] = s1;
            }
        }
        __syncthreads();
        if (tid < 128) {
            float t = part[0][tid] + part[1][tid] + part[2][tid] + part[3][tid];
            g_part[blockIdx.x][m0 + tid] = t;
        }
    }
}

// ============================================================================
// Finish: out[b] = fm[b]*Wout[0] + b_out + sum_p g_part[p][b]
// ============================================================================
__global__ void finish_kernel(const float* __restrict__ Wout,
                              const float* __restrict__ bout,
                              float* __restrict__ out) {
    int b = blockIdx.x * blockDim.x + threadIdx.x;
    if (b >= B_) return;
    float s = g_part[0][b] + g_part[1][b] + g_part[2][b] + g_part[3][b];
    out[b] = fmaf(g_fm[b], Wout[0], bout[0] + s);
}

// ============================================================================
// Launch
// ============================================================================
static void* sym_addr(const void* symbol) {
    void* p = nullptr;
    cudaGetSymbolAddress(&p, symbol);
    return p;
}

extern "C" void kernel_launch(void* const* d_in, const int* in_sizes, int n_in,
                              void* d_out, int out_size) {
    const float* cont    = (const float*)d_in[0];
    const int*   cat     = (const int*)  d_in[1];
    const float* w_cont  = (const float*)d_in[2];
    const float* b_cont  = (const float*)d_in[3];
    const float* t_first = (const float*)d_in[4];
    const float* t_emb   = (const float*)d_in[5];
    const float* W1      = (const float*)d_in[6];
    const float* b1      = (const float*)d_in[7];
    const float* W2      = (const float*)d_in[8];
    const float* b2      = (const float*)d_in[9];
    const float* Wout    = (const float*)d_in[10];
    const float* bout    = (const float*)d_in[11];
    float* out = (float*)d_out;

    const int SMEM_DYN = 2 * STAGE_;
    cudaFuncSetAttribute(gemm_fp16x2<false>, cudaFuncAttributeMaxDynamicSharedMemorySize, SMEM_DYN);
    cudaFuncSetAttribute(gemm_fp16x2<true>,  cudaFuncAttributeMaxDynamicSharedMemorySize, SMEM_DYN);

    __half* dnnh = (__half*)sym_addr(g_dnnh);
    __half* dnnl = (__half*)sym_addr(g_dnnl);
    __half* h1h  = (__half*)sym_addr(g_h1h);
    __half* h1l  = (__half*)sym_addr(g_h1l);
    __half* w1t  = (__half*)sym_addr(g_w1t);
    __half* w2t  = (__half*)sym_addr(g_w2t);

    // 1) weight prep (transpose + pad + fp16 round)
    prep_kernel<<<(NPAD_ * LDA1_ + 255) / 256, 256>>>(W1, W2);

    // 2) gather + FM + dnn_in (fp16 hi/lo)
    gather_fm_kernel<<<B_ / 8, 256>>>(cont, cat, w_cont, b_cont, t_first, t_emb);

    // 3) h1 = relu(dnn_in @ W1 + b1)
    dim3 grid(4, B_ / 128);
    gemm_fp16x2<false><<<grid, 512, SMEM_DYN>>>(dnnh, dnnl, w1t, LDA1_,
                                                b1, nullptr, h1h, h1l, K2PAD_, LDA1_ / 32);

    // 4) fused: h2 = relu(h1 @ W2 + b2); g_part = per-tile dot(h2, Wout[1:])
    gemm_fp16x2<true><<<grid, 512, SMEM_DYN>>>(h1h, h1l, w2t, K2PAD_,
                                               b2, Wout, nullptr, nullptr, 0, K2PAD_ / 32);

    // 5) out = fm*Wout[0] + b_out + parts
    finish_kernel<<<B_ / 256, 256>>>(Wout, bout, out);
}

// round 7
// speedup vs baseline: 3.5924x; 1.2543x over previous
#include <cuda_runtime.h>
#include <cuda_bf16.h>
#include <cuda_fp16.h>
#include <cstdint>

// ---------------- Problem constants ----------------
#define B_     16384
#define F_     26
#define V_     100000
#define E_     16
#define CONT_  13
#define K1_    429     // CONT_ + F_*E_
#define LDA1_  448     // K1_ padded to multiple of 32
#define K2PAD_ 416     // H_(400) padded to multiple of 32
#define H_     400
#define NT_    80      // CTA N tile (5 * 80 = 400, exact)

// ---------------- Scratch (device globals) ----------------
__device__ __align__(256) __half g_dnnh[(size_t)B_ * LDA1_];
__device__ __align__(256) __half g_dnnl[(size_t)B_ * LDA1_];
// h1 cols 400..415 are NEVER written -> stay zero-initialized (K padding for GEMM2)
__device__ __align__(256) __half g_h1h [(size_t)B_ * K2PAD_];
__device__ __align__(256) __half g_h1l [(size_t)B_ * K2PAD_];
__device__ __align__(256) __half g_w1t [(size_t)H_ * LDA1_];   // [n][k] = fp16(W1[k][n])
__device__ __align__(256) __half g_w2t [(size_t)H_ * K2PAD_];  // [n][k] = fp16(W2[k][n])
__device__ float g_fm  [B_];
__device__ float g_part[5][B_];

// ---------------- PTX helpers ----------------
__device__ __forceinline__ uint32_t smem_u32(const void* p) {
    return (uint32_t)__cvta_generic_to_shared(p);
}
#define CP16(dst_u32, src) \
    asm volatile("cp.async.cg.shared.global [%0], [%1], 16;" :: "r"(dst_u32), "l"(src))
#define CP_COMMIT() asm volatile("cp.async.commit_group;" ::: "memory")
#define CP_WAIT0()  asm volatile("cp.async.wait_group 0;" ::: "memory")
#define CP_WAIT1()  asm volatile("cp.async.wait_group 1;" ::: "memory")

#define LDSM_X4(r0, r1, r2, r3, addr)                                          \
    asm volatile("ldmatrix.sync.aligned.m8n8.x4.shared.b16 {%0,%1,%2,%3},[%4];"\
                 : "=r"(r0), "=r"(r1), "=r"(r2), "=r"(r3) : "r"(addr))
#define LDSM_X2(r0, r1, addr)                                                  \
    asm volatile("ldmatrix.sync.aligned.m8n8.x2.shared.b16 {%0,%1},[%2];"      \
                 : "=r"(r0), "=r"(r1) : "r"(addr))

__device__ __forceinline__ void mma_fp16(float* c,
                                         uint32_t a0, uint32_t a1, uint32_t a2, uint32_t a3,
                                         uint32_t b0, uint32_t b1) {
    asm volatile(
        "mma.sync.aligned.m16n8k16.row.col.f32.f16.f16.f32 "
        "{%0,%1,%2,%3},{%4,%5,%6,%7},{%8,%9},{%0,%1,%2,%3};"
        : "+f"(c[0]), "+f"(c[1]), "+f"(c[2]), "+f"(c[3])
        : "r"(a0), "r"(a1), "r"(a2), "r"(a3), "r"(b0), "r"(b1));
}

__device__ __forceinline__ void split_fp16(float x, __half& h, __half& l) {
    h = __float2half_rn(x);
    l = __float2half_rn(x - __half2float(h));
}

// ============================================================================
// Kernel 1: gather + FM; emits dnn_in as fp16 hi/lo (one warp per sample)
// ============================================================================
__global__ void gather_fm_kernel(const float* __restrict__ cont,
                                 const int*   __restrict__ cat,
                                 const float* __restrict__ w_cont,
                                 const float* __restrict__ b_cont,
                                 const float* __restrict__ t_first,
                                 const float* __restrict__ t_emb) {
    int warp = (blockIdx.x * blockDim.x + threadIdx.x) >> 5;
    int lane = threadIdx.x & 31;
    if (warp >= B_) return;
    const int b = warp;

    float v[16];
    #pragma unroll
    for (int i = 0; i < 16; i++) v[i] = 0.f;
    float q = 0.f, scal = 0.f;

    if (lane < F_) {
        int idx = cat[b * F_ + lane];
        const float4* row =
            reinterpret_cast<const float4*>(t_emb + ((size_t)lane * V_ + (size_t)idx) * E_);
        float4 r0 = row[0], r1 = row[1], r2 = row[2], r3 = row[3];
        v[0]=r0.x; v[1]=r0.y; v[2]=r0.z; v[3]=r0.w;
        v[4]=r1.x; v[5]=r1.y; v[6]=r1.z; v[7]=r1.w;
        v[8]=r2.x; v[9]=r2.y; v[10]=r2.z; v[11]=r2.w;
        v[12]=r3.x; v[13]=r3.y; v[14]=r3.z; v[15]=r3.w;

        size_t base = (size_t)b * LDA1_ + CONT_ + lane * E_;
        #pragma unroll
        for (int i = 0; i < 16; i++) {
            __half h, l;
            split_fp16(v[i], h, l);
            g_dnnh[base + i] = h;
            g_dnnl[base + i] = l;
            q = fmaf(v[i], v[i], q);
        }
        scal = t_first[(size_t)lane * V_ + (size_t)idx];
    }
    if (lane < CONT_) {
        float c = cont[b * CONT_ + lane];
        __half h, l;
        split_fp16(c, h, l);
        g_dnnh[(size_t)b * LDA1_ + lane] = h;
        g_dnnl[(size_t)b * LDA1_ + lane] = l;
        scal = fmaf(c, w_cont[lane], scal);
    }
    if (lane < LDA1_ - K1_) {   // zero pad cols 429..447
        g_dnnh[(size_t)b * LDA1_ + K1_ + lane] = __float2half_rn(0.f);
        g_dnnl[(size_t)b * LDA1_ + K1_ + lane] = __float2half_rn(0.f);
    }

    #pragma unroll
    for (int off = 16; off; off >>= 1) {
        #pragma unroll
        for (int e = 0; e < 16; e++)
            v[e] += __shfl_xor_sync(0xffffffffu, v[e], off);
        q    += __shfl_xor_sync(0xffffffffu, q,    off);
        scal += __shfl_xor_sync(0xffffffffu, scal, off);
    }
    if (lane == 0) {
        float ss = 0.f;
        #pragma unroll
        for (int e = 0; e < 16; e++) ss = fmaf(v[e], v[e], ss);
        g_fm[b] = scal + b_cont[0] + 0.5f * (ss - q);
    }
}

// ============================================================================
// Prep: transpose + pad weights into fp16 K-major buffers
// ============================================================================
__global__ void prep_kernel(const float* __restrict__ W1, const float* __restrict__ W2) {
    int idx = blockIdx.x * blockDim.x + threadIdx.x;
    if (idx < H_ * LDA1_) {                  // W1T: [400][448]
        int n = idx / LDA1_, k = idx % LDA1_;
        float v = (k < K1_) ? W1[(size_t)k * H_ + n] : 0.f;
        g_w1t[idx] = __float2half_rn(v);
    }
    if (idx < H_ * K2PAD_) {                 // W2T: [400][416]
        int n = idx / K2PAD_, k = idx % K2PAD_;
        float v = (k < H_) ? W2[(size_t)k * H_ + n] : 0.f;
        g_w2t[idx] = __float2half_rn(v);
    }
}

// ============================================================================
// fp16 2-term GEMM via mma.sync m16n8k16.
//   CTA tile 128(M) x 80(N), 8 warps (4M x 2N), warp tile 32x40, 256 threads.
//   C = (Ah + Al) @ Bh^T ; BK=32, double-buffered cp.async.
//   N=400 handled exactly (5 CTA cols), no N bounds checks anywhere.
//   FUSE=0: relu(+bias) -> Ch/Cl fp16 hi/lo.  FUSE=1: fused dot w/ Wout -> g_part.
// ============================================================================
#define OFF_AH 0
#define OFF_AL 10240
#define OFF_BH 20480
#define STAGE_ 26880    // 10240*2 + 80*80

template<bool FUSE>
__global__ void __launch_bounds__(256, 2)
gemm_fp16x2(const __half* __restrict__ Ah, const __half* __restrict__ Al,
            const __half* __restrict__ Bh,
            int ldk,                           // K stride (padded)
            const float* __restrict__ bias,    // [H_]
            const float* __restrict__ Wout,    // [1+H_] (FUSE)
            __half* __restrict__ Ch, __half* __restrict__ Cl, // (!FUSE)
            int ldc, int NKB) {
    extern __shared__ char smem_raw[];
    __shared__ float part[2][128];
    const uint32_t sbase = smem_u32(smem_raw);

    const int tid  = threadIdx.x;
    const int warp = tid >> 5, lane = tid & 31;
    const int gr = lane >> 2, gc = lane & 3;
    const int wm  = (warp >> 1) * 32;    // warp row band (0..96)
    const int wni = warp & 1;
    const int wn  = wni * 40;            // warp col band (0 or 40)
    const int m0 = blockIdx.y * 128;
    const int n0 = blockIdx.x * NT_;

    const int lane8 = lane & 7;
    const int laneH = (lane >> 3) & 1;
    const int laneK = lane >> 4;
    const uint32_t aoff  = (uint32_t)((wm + lane8 + laneH * 8) * 80 + laneK * 16);
    const uint32_t boff4 = (uint32_t)((wn + lane8 + laneK * 8) * 80 + laneH * 16);
    const uint32_t boff2 = (uint32_t)((wn + 32 + lane8) * 80 + laneH * 16);

    float acc[2][5][4];
    #pragma unroll
    for (int i = 0; i < 2; i++)
        #pragma unroll
        for (int j = 0; j < 5; j++)
            #pragma unroll
            for (int k = 0; k < 4; k++) acc[i][j][k] = 0.f;

    // ---- tile loader ----
    // A: 512 chunks per array (2/thread each for hi+lo); B: 320 chunks (1 + pred).
    const int arow0 = tid >> 1,            aq0 = (tid & 1) << 1;        // unused helper
    (void)arow0; (void)aq0;
    #define LOAD_KB(KB, BUF)                                                        \
    do {                                                                            \
        const int k0_ = (KB) * 32;                                                  \
        const uint32_t st_ = sbase + (BUF) * STAGE_;                                \
        _Pragma("unroll")                                                           \
        for (int h = 0; h < 2; h++) {                                               \
            int c_ = tid + h * 256;                                                 \
            int row_ = c_ >> 2, q_ = c_ & 3;                                        \
            uint32_t d_ = st_ + row_ * 80 + q_ * 16;                                \
            CP16(d_ + OFF_AH, Ah + (size_t)(m0 + row_) * ldk + k0_ + q_ * 8);       \
            CP16(d_ + OFF_AL, Al + (size_t)(m0 + row_) * ldk + k0_ + q_ * 8);       \
        }                                                                           \
        {                                                                           \
            int row_ = tid >> 2, q_ = tid & 3;                                      \
            uint32_t d_ = st_ + OFF_BH + row_ * 80 + q_ * 16;                       \
            CP16(d_, Bh + (size_t)(n0 + row_) * ldk + k0_ + q_ * 8);                \
        }                                                                           \
        if (tid < 64) {                                                             \
            int c_ = 256 + tid;                                                     \
            int row_ = c_ >> 2, q_ = c_ & 3;                                        \
            uint32_t d_ = st_ + OFF_BH + row_ * 80 + q_ * 16;                       \
            CP16(d_, Bh + (size_t)(n0 + row_) * ldk + k0_ + q_ * 8);                \
        }                                                                           \
    } while (0)

    LOAD_KB(0, 0);
    CP_COMMIT();

    for (int kb = 0; kb < NKB; kb++) {
        const int buf = kb & 1;
        if (kb + 1 < NKB) { LOAD_KB(kb + 1, buf ^ 1); CP_COMMIT(); CP_WAIT1(); }
        else              { CP_WAIT0(); }
        __syncthreads();

        const uint32_t st = sbase + buf * STAGE_;
        #pragma unroll
        for (int ks = 0; ks < 2; ks++) {
            const uint32_t ko = ks * 32;   // 16 fp16 = 32B
            uint32_t ah[2][4], al[2][4], bh[5][2];
            #pragma unroll
            for (int mi = 0; mi < 2; mi++) {
                uint32_t ad = st + aoff + mi * 1280 + ko;
                LDSM_X4(ah[mi][0], ah[mi][1], ah[mi][2], ah[mi][3], ad + OFF_AH);
                LDSM_X4(al[mi][0], al[mi][1], al[mi][2], al[mi][3], ad + OFF_AL);
            }
            #pragma unroll
            for (int nj = 0; nj < 2; nj++) {
                uint32_t bd = st + OFF_BH + boff4 + nj * 1280 + ko;
                LDSM_X4(bh[nj*2][0], bh[nj*2][1], bh[nj*2+1][0], bh[nj*2+1][1], bd);
            }
            LDSM_X2(bh[4][0], bh[4][1], st + OFF_BH + boff2 + ko);

            #pragma unroll
            for (int mi = 0; mi < 2; mi++)
                #pragma unroll
                for (int ni = 0; ni < 5; ni++) {
                    mma_fp16(acc[mi][ni], ah[mi][0], ah[mi][1], ah[mi][2], ah[mi][3],
                             bh[ni][0], bh[ni][1]);
                    mma_fp16(acc[mi][ni], al[mi][0], al[mi][1], al[mi][2], al[mi][3],
                             bh[ni][0], bh[ni][1]);
                }
        }
        __syncthreads();
    }
    #undef LOAD_KB

    // ---- epilogue (n always < 400: no N checks) ----
    if (!FUSE) {
        #pragma unroll
        for (int mi = 0; mi < 2; mi++) {
            int r = m0 + wm + mi * 16 + gr;
            #pragma unroll
            for (int ni = 0; ni < 5; ni++) {
                int n = n0 + wn + ni * 8 + gc * 2;
                float b0v = bias[n], b1v = bias[n + 1];
                #pragma unroll
                for (int half = 0; half < 2; half++) {
                    float x0 = fmaxf(acc[mi][ni][half * 2 + 0] + b0v, 0.f);
                    float x1 = fmaxf(acc[mi][ni][half * 2 + 1] + b1v, 0.f);
                    __half h0, l0, h1, l1;
                    split_fp16(x0, h0, l0);
                    split_fp16(x1, h1, l1);
                    uint32_t ph = (uint32_t)__half_as_ushort(h0) |
                                  ((uint32_t)__half_as_ushort(h1) << 16);
                    uint32_t pl = (uint32_t)__half_as_ushort(l0) |
                                  ((uint32_t)__half_as_ushort(l1) << 16);
                    size_t o = (size_t)(r + half * 8) * ldc + n;
                    *reinterpret_cast<uint32_t*>(Ch + o) = ph;
                    *reinterpret_cast<uint32_t*>(Cl + o) = pl;
                }
            }
        }
    } else {
        #pragma unroll
        for (int mi = 0; mi < 2; mi++) {
            float s0 = 0.f, s1 = 0.f;
            #pragma unroll
            for (int ni = 0; ni < 5; ni++) {
                int n = n0 + wn + ni * 8 + gc * 2;
                float w0v = Wout[1 + n], w1v = Wout[2 + n];
                float b0v = bias[n],     b1v = bias[n + 1];
                s0 = fmaf(fmaxf(acc[mi][ni][0] + b0v, 0.f), w0v, s0);
                s0 = fmaf(fmaxf(acc[mi][ni][1] + b1v, 0.f), w1v, s0);
                s1 = fmaf(fmaxf(acc[mi][ni][2] + b0v, 0.f), w0v, s1);
                s1 = fmaf(fmaxf(acc[mi][ni][3] + b1v, 0.f), w1v, s1);
            }
            s0 += __shfl_xor_sync(0xffffffffu, s0, 1);
            s0 += __shfl_xor_sync(0xffffffffu, s0, 2);
            s1 += __shfl_xor_sync(0xffffffffu, s1, 1);
            s1 += __shfl_xor_sync(0xffffffffu, s1, 2);
            if (gc == 0) {
                part[wni][wm + mi * 16 + gr]     = s0;
                part[wni][wm + mi * 16 + gr + 8] = s1;
            }
        }
        __syncthreads();
        if (tid < 128) {
            g_part[blockIdx.x][m0 + tid] = part[0][tid] + part[1][tid];
        }
    }
}

// ============================================================================
// Finish: out[b] = fm[b]*Wout[0] + b_out + sum_p g_part[p][b]
// ============================================================================
__global__ void finish_kernel(const float* __restrict__ Wout,
                              const float* __restrict__ bout,
                              float* __restrict__ out) {
    int b = blockIdx.x * blockDim.x + threadIdx.x;
    if (b >= B_) return;
    float s = g_part[0][b] + g_part[1][b] + g_part[2][b] + g_part[3][b] + g_part[4][b];
    out[b] = fmaf(g_fm[b], Wout[0], bout[0] + s);
}

// ============================================================================
// Launch
// ============================================================================
static void* sym_addr(const void* symbol) {
    void* p = nullptr;
    cudaGetSymbolAddress(&p, symbol);
    return p;
}

extern "C" void kernel_launch(void* const* d_in, const int* in_sizes, int n_in,
                              void* d_out, int out_size) {
    const float* cont    = (const float*)d_in[0];
    const int*   cat     = (const int*)  d_in[1];
    const float* w_cont  = (const float*)d_in[2];
    const float* b_cont  = (const float*)d_in[3];
    const float* t_first = (const float*)d_in[4];
    const float* t_emb   = (const float*)d_in[5];
    const float* W1      = (const float*)d_in[6];
    const float* b1      = (const float*)d_in[7];
    const float* W2      = (const float*)d_in[8];
    const float* b2      = (const float*)d_in[9];
    const float* Wout    = (const float*)d_in[10];
    const float* bout    = (const float*)d_in[11];
    float* out = (float*)d_out;

    const int SMEM_DYN = 2 * STAGE_;
    cudaFuncSetAttribute(gemm_fp16x2<false>, cudaFuncAttributeMaxDynamicSharedMemorySize, SMEM_DYN);
    cudaFuncSetAttribute(gemm_fp16x2<true>,  cudaFuncAttributeMaxDynamicSharedMemorySize, SMEM_DYN);

    __half* dnnh = (__half*)sym_addr(g_dnnh);
    __half* dnnl = (__half*)sym_addr(g_dnnl);
    __half* h1h  = (__half*)sym_addr(g_h1h);
    __half* h1l  = (__half*)sym_addr(g_h1l);
    __half* w1t  = (__half*)sym_addr(g_w1t);
    __half* w2t  = (__half*)sym_addr(g_w2t);

    // 1) weight prep (transpose + pad + fp16 round)
    prep_kernel<<<(H_ * LDA1_ + 255) / 256, 256>>>(W1, W2);

    // 2) gather + FM + dnn_in (fp16 hi/lo)
    gather_fm_kernel<<<B_ / 8, 256>>>(cont, cat, w_cont, b_cont, t_first, t_emb);

    // 3) h1 = relu(dnn_in @ W1 + b1)     grid: 5 N-tiles x 128 M-tiles
    dim3 grid(5, B_ / 128);
    gemm_fp16x2<false><<<grid, 256, SMEM_DYN>>>(dnnh, dnnl, w1t, LDA1_,
                                                b1, nullptr, h1h, h1l, K2PAD_, LDA1_ / 32);

    // 4) fused: h2 = relu(h1 @ W2 + b2); g_part = per-tile dot(h2, Wout[1:])
    gemm_fp16x2<true><<<grid, 256, SMEM_DYN>>>(h1h, h1l, w2t, K2PAD_,
                                               b2, Wout, nullptr, nullptr, 0, K2PAD_ / 32);

    // 5) out = fm*Wout[0] + b_out + parts
    finish_kernel<<<B_ / 256, 256>>>(Wout, bout, out);
}

// round 8
// speedup vs baseline: 5.5139x; 1.5349x over previous
#include <cuda_runtime.h>
#include <cuda_bf16.h>
#include <cuda_fp16.h>
#include <cstdint>

// ---------------- Problem constants ----------------
#define B_     16384
#define F_     26
#define V_     100000
#define E_     16
#define CONT_  13
#define K1_    429     // CONT_ + F_*E_
#define LDA1_  448     // K1_ padded to multiple of 32
#define K2PAD_ 416     // H_(400) padded to multiple of 32
#define H_     400
#define NT_    80      // CTA N tile (5 * 80 = 400, exact)

// ---------------- Scratch (device globals) ----------------
__device__ __align__(256) __half g_dnn [(size_t)B_ * LDA1_];
// h1 cols 400..415 are NEVER written -> stay zero-initialized (K padding for GEMM2)
__device__ __align__(256) __half g_h1  [(size_t)B_ * K2PAD_];
__device__ __align__(256) __half g_w1t [(size_t)H_ * LDA1_];   // [n][k] = fp16(W1[k][n])
__device__ __align__(256) __half g_w2t [(size_t)H_ * K2PAD_];  // [n][k] = fp16(W2[k][n])
__device__ float g_fm  [B_];
__device__ float g_part[5][B_];

// ---------------- PTX helpers ----------------
__device__ __forceinline__ uint32_t smem_u32(const void* p) {
    return (uint32_t)__cvta_generic_to_shared(p);
}
#define CP16(dst_u32, src) \
    asm volatile("cp.async.cg.shared.global [%0], [%1], 16;" :: "r"(dst_u32), "l"(src))
#define CP_COMMIT() asm volatile("cp.async.commit_group;" ::: "memory")
#define CP_WAIT0()  asm volatile("cp.async.wait_group 0;" ::: "memory")
#define CP_WAIT1()  asm volatile("cp.async.wait_group 1;" ::: "memory")

#define LDSM_X4(r0, r1, r2, r3, addr)                                          \
    asm volatile("ldmatrix.sync.aligned.m8n8.x4.shared.b16 {%0,%1,%2,%3},[%4];"\
                 : "=r"(r0), "=r"(r1), "=r"(r2), "=r"(r3) : "r"(addr))
#define LDSM_X2(r0, r1, addr)                                                  \
    asm volatile("ldmatrix.sync.aligned.m8n8.x2.shared.b16 {%0,%1},[%2];"      \
                 : "=r"(r0), "=r"(r1) : "r"(addr))

__device__ __forceinline__ void mma_fp16(float* c,
                                         uint32_t a0, uint32_t a1, uint32_t a2, uint32_t a3,
                                         uint32_t b0, uint32_t b1) {
    asm volatile(
        "mma.sync.aligned.m16n8k16.row.col.f32.f16.f16.f32 "
        "{%0,%1,%2,%3},{%4,%5,%6,%7},{%8,%9},{%0,%1,%2,%3};"
        : "+f"(c[0]), "+f"(c[1]), "+f"(c[2]), "+f"(c[3])
        : "r"(a0), "r"(a1), "r"(a2), "r"(a3), "r"(b0), "r"(b1));
}

// ============================================================================
// Kernel 1: gather + FM; emits dnn_in as fp16 (one warp per sample)
// ============================================================================
__global__ void gather_fm_kernel(const float* __restrict__ cont,
                                 const int*   __restrict__ cat,
                                 const float* __restrict__ w_cont,
                                 const float* __restrict__ b_cont,
                                 const float* __restrict__ t_first,
                                 const float* __restrict__ t_emb) {
    int warp = (blockIdx.x * blockDim.x + threadIdx.x) >> 5;
    int lane = threadIdx.x & 31;
    if (warp >= B_) return;
    const int b = warp;

    float v[16];
    #pragma unroll
    for (int i = 0; i < 16; i++) v[i] = 0.f;
    float q = 0.f, scal = 0.f;

    if (lane < F_) {
        int idx = cat[b * F_ + lane];
        const float4* row =
            reinterpret_cast<const float4*>(t_emb + ((size_t)lane * V_ + (size_t)idx) * E_);
        float4 r0 = row[0], r1 = row[1], r2 = row[2], r3 = row[3];
        v[0]=r0.x; v[1]=r0.y; v[2]=r0.z; v[3]=r0.w;
        v[4]=r1.x; v[5]=r1.y; v[6]=r1.z; v[7]=r1.w;
        v[8]=r2.x; v[9]=r2.y; v[10]=r2.z; v[11]=r2.w;
        v[12]=r3.x; v[13]=r3.y; v[14]=r3.z; v[15]=r3.w;

        // pack 16 fp16 and store as 2 x 16B
        uint32_t pk[8];
        #pragma unroll
        for (int i = 0; i < 8; i++) {
            __half h0 = __float2half_rn(v[2*i]);
            __half h1 = __float2half_rn(v[2*i+1]);
            pk[i] = (uint32_t)__half_as_ushort(h0) | ((uint32_t)__half_as_ushort(h1) << 16);
            q = fmaf(v[2*i],   v[2*i],   q);
            q = fmaf(v[2*i+1], v[2*i+1], q);
        }
        __half* dst = g_dnn + (size_t)b * LDA1_ + CONT_ + lane * E_;
        // CONT_=13 odd -> dst 2B-aligned only; store as 8 x u32? dst+? 13+16*lane: odd half offset
        // -> byte address = 2*(13+16*lane) = 26 + 32*lane : 2-aligned only. Use ushort stores.
        #pragma unroll
        for (int i = 0; i < 8; i++) {
            dst[2*i]   = __ushort_as_half((unsigned short)(pk[i] & 0xffff));
            dst[2*i+1] = __ushort_as_half((unsigned short)(pk[i] >> 16));
        }
        scal = t_first[(size_t)lane * V_ + (size_t)idx];
    }
    if (lane < CONT_) {
        float c = cont[b * CONT_ + lane];
        g_dnn[(size_t)b * LDA1_ + lane] = __float2half_rn(c);
        scal = fmaf(c, w_cont[lane], scal);
    }
    if (lane < LDA1_ - K1_) {   // zero pad cols 429..447
        g_dnn[(size_t)b * LDA1_ + K1_ + lane] = __float2half_rn(0.f);
    }

    #pragma unroll
    for (int off = 16; off; off >>= 1) {
        #pragma unroll
        for (int e = 0; e < 16; e++)
            v[e] += __shfl_xor_sync(0xffffffffu, v[e], off);
        q    += __shfl_xor_sync(0xffffffffu, q,    off);
        scal += __shfl_xor_sync(0xffffffffu, scal, off);
    }
    if (lane == 0) {
        float ss = 0.f;
        #pragma unroll
        for (int e = 0; e < 16; e++) ss = fmaf(v[e], v[e], ss);
        g_fm[b] = scal + b_cont[0] + 0.5f * (ss - q);
    }
}

// ============================================================================
// Prep: transpose + pad weights into fp16 K-major buffers
// ============================================================================
__global__ void prep_kernel(const float* __restrict__ W1, const float* __restrict__ W2) {
    int idx = blockIdx.x * blockDim.x + threadIdx.x;
    if (idx < H_ * LDA1_) {                  // W1T: [400][448]
        int n = idx / LDA1_, k = idx % LDA1_;
        float v = (k < K1_) ? W1[(size_t)k * H_ + n] : 0.f;
        g_w1t[idx] = __float2half_rn(v);
    }
    if (idx < H_ * K2PAD_) {                 // W2T: [400][416]
        int n = idx / K2PAD_, k = idx % K2PAD_;
        float v = (k < H_) ? W2[(size_t)k * H_ + n] : 0.f;
        g_w2t[idx] = __float2half_rn(v);
    }
}

// ============================================================================
// Single-fp16 GEMM via mma.sync m16n8k16 (1 mma per k16 step).
//   CTA tile 128(M) x 80(N), 8 warps (4M x 2N), warp tile 32x40, 256 threads.
//   BK=32, double-buffered cp.async. SMEM rows padded to 80B.
//   FUSE=0: relu(+bias) -> C fp16.  FUSE=1: fused dot w/ Wout -> g_part.
// ============================================================================
#define OFF_A  0
#define OFF_B  10240
#define STAGE_ 16640    // 10240 + 80*80

template<bool FUSE>
__global__ void __launch_bounds__(256, 2)
gemm_fp16(const __half* __restrict__ A,
          const __half* __restrict__ Bh,
          int ldk,                           // K stride (padded)
          const float* __restrict__ bias,    // [H_]
          const float* __restrict__ Wout,    // [1+H_] (FUSE)
          __half* __restrict__ C,            // (!FUSE)
          int ldc, int NKB) {
    extern __shared__ char smem_raw[];
    __shared__ float part[2][128];
    const uint32_t sbase = smem_u32(smem_raw);

    const int tid  = threadIdx.x;
    const int warp = tid >> 5, lane = tid & 31;
    const int gr = lane >> 2, gc = lane & 3;
    const int wm  = (warp >> 1) * 32;    // warp row band (0..96)
    const int wni = warp & 1;
    const int wn  = wni * 40;            // warp col band (0 or 40)
    const int m0 = blockIdx.y * 128;
    const int n0 = blockIdx.x * NT_;

    const int lane8 = lane & 7;
    const int laneH = (lane >> 3) & 1;
    const int laneK = lane >> 4;
    const uint32_t aoff  = (uint32_t)((wm + lane8 + laneH * 8) * 80 + laneK * 16);
    const uint32_t boff4 = (uint32_t)((wn + lane8 + laneK * 8) * 80 + laneH * 16);
    const uint32_t boff2 = (uint32_t)((wn + 32 + lane8) * 80 + laneH * 16);

    float acc[2][5][4];
    #pragma unroll
    for (int i = 0; i < 2; i++)
        #pragma unroll
        for (int j = 0; j < 5; j++)
            #pragma unroll
            for (int k = 0; k < 4; k++) acc[i][j][k] = 0.f;

    // ---- tile loader: A 512 chunks (2/thread), B 320 chunks (1 + pred) ----
    #define LOAD_KB(KB, BUF)                                                        \
    do {                                                                            \
        const int k0_ = (KB) * 32;                                                  \
        const uint32_t st_ = sbase + (BUF) * STAGE_;                                \
        _Pragma("unroll")                                                           \
        for (int h = 0; h < 2; h++) {                                               \
            int c_ = tid + h * 256;                                                 \
            int row_ = c_ >> 2, q_ = c_ & 3;                                        \
            uint32_t d_ = st_ + OFF_A + row_ * 80 + q_ * 16;                        \
            CP16(d_, A + (size_t)(m0 + row_) * ldk + k0_ + q_ * 8);                 \
        }                                                                           \
        {                                                                           \
            int row_ = tid >> 2, q_ = tid & 3;                                      \
            uint32_t d_ = st_ + OFF_B + row_ * 80 + q_ * 16;                        \
            CP16(d_, Bh + (size_t)(n0 + row_) * ldk + k0_ + q_ * 8);                \
        }                                                                           \
        if (tid < 64) {                                                             \
            int c_ = 256 + tid;                                                     \
            int row_ = c_ >> 2, q_ = c_ & 3;                                        \
            uint32_t d_ = st_ + OFF_B + row_ * 80 + q_ * 16;                        \
            CP16(d_, Bh + (size_t)(n0 + row_) * ldk + k0_ + q_ * 8);                \
        }                                                                           \
    } while (0)

    LOAD_KB(0, 0);
    CP_COMMIT();

    for (int kb = 0; kb < NKB; kb++) {
        const int buf = kb & 1;
        if (kb + 1 < NKB) { LOAD_KB(kb + 1, buf ^ 1); CP_COMMIT(); CP_WAIT1(); }
        else              { CP_WAIT0(); }
        __syncthreads();

        const uint32_t st = sbase + buf * STAGE_;
        #pragma unroll
        for (int ks = 0; ks < 2; ks++) {
            const uint32_t ko = ks * 32;   // 16 fp16 = 32B
            uint32_t ah[2][4], bh[5][2];
            #pragma unroll
            for (int mi = 0; mi < 2; mi++) {
                uint32_t ad = st + OFF_A + aoff + mi * 1280 + ko;
                LDSM_X4(ah[mi][0], ah[mi][1], ah[mi][2], ah[mi][3], ad);
            }
            #pragma unroll
            for (int nj = 0; nj < 2; nj++) {
                uint32_t bd = st + OFF_B + boff4 + nj * 1280 + ko;
                LDSM_X4(bh[nj*2][0], bh[nj*2][1], bh[nj*2+1][0], bh[nj*2+1][1], bd);
            }
            LDSM_X2(bh[4][0], bh[4][1], st + OFF_B + boff2 + ko);

            #pragma unroll
            for (int mi = 0; mi < 2; mi++)
                #pragma unroll
                for (int ni = 0; ni < 5; ni++)
                    mma_fp16(acc[mi][ni], ah[mi][0], ah[mi][1], ah[mi][2], ah[mi][3],
                             bh[ni][0], bh[ni][1]);
        }
        __syncthreads();
    }
    #undef LOAD_KB

    // ---- epilogue (n always < 400: no N checks) ----
    if (!FUSE) {
        #pragma unroll
        for (int mi = 0; mi < 2; mi++) {
            int r = m0 + wm + mi * 16 + gr;
            #pragma unroll
            for (int ni = 0; ni < 5; ni++) {
                int n = n0 + wn + ni * 8 + gc * 2;
                float b0v = bias[n], b1v = bias[n + 1];
                #pragma unroll
                for (int half = 0; half < 2; half++) {
                    float x0 = fmaxf(acc[mi][ni][half * 2 + 0] + b0v, 0.f);
                    float x1 = fmaxf(acc[mi][ni][half * 2 + 1] + b1v, 0.f);
                    __half h0 = __float2half_rn(x0);
                    __half h1 = __float2half_rn(x1);
                    uint32_t ph = (uint32_t)__half_as_ushort(h0) |
                                  ((uint32_t)__half_as_ushort(h1) << 16);
                    size_t o = (size_t)(r + half * 8) * ldc + n;
                    *reinterpret_cast<uint32_t*>(C + o) = ph;
                }
            }
        }
    } else {
        #pragma unroll
        for (int mi = 0; mi < 2; mi++) {
            float s0 = 0.f, s1 = 0.f;
            #pragma unroll
            for (int ni = 0; ni < 5; ni++) {
                int n = n0 + wn + ni * 8 + gc * 2;
                float w0v = Wout[1 + n], w1v = Wout[2 + n];
                float b0v = bias[n],     b1v = bias[n + 1];
                s0 = fmaf(fmaxf(acc[mi][ni][0] + b0v, 0.f), w0v, s0);
                s0 = fmaf(fmaxf(acc[mi][ni][1] + b1v, 0.f), w1v, s0);
                s1 = fmaf(fmaxf(acc[mi][ni][2] + b0v, 0.f), w0v, s1);
                s1 = fmaf(fmaxf(acc[mi][ni][3] + b1v, 0.f), w1v, s1);
            }
            s0 += __shfl_xor_sync(0xffffffffu, s0, 1);
            s0 += __shfl_xor_sync(0xffffffffu, s0, 2);
            s1 += __shfl_xor_sync(0xffffffffu, s1, 1);
            s1 += __shfl_xor_sync(0xffffffffu, s1, 2);
            if (gc == 0) {
                part[wni][wm + mi * 16 + gr]     = s0;
                part[wni][wm + mi * 16 + gr + 8] = s1;
            }
        }
        __syncthreads();
        if (tid < 128) {
            g_part[blockIdx.x][m0 + tid] = part[0][tid] + part[1][tid];
        }
    }
}

// ============================================================================
// Finish: out[b] = fm[b]*Wout[0] + b_out + sum_p g_part[p][b]
// ============================================================================
__global__ void finish_kernel(const float* __restrict__ Wout,
                              const float* __restrict__ bout,
                              float* __restrict__ out) {
    int b = blockIdx.x * blockDim.x + threadIdx.x;
    if (b >= B_) return;
    float s = g_part[0][b] + g_part[1][b] + g_part[2][b] + g_part[3][b] + g_part[4][b];
    out[b] = fmaf(g_fm[b], Wout[0], bout[0] + s);
}

// ============================================================================
// Launch
// ============================================================================
static void* sym_addr(const void* symbol) {
    void* p = nullptr;
    cudaGetSymbolAddress(&p, symbol);
    return p;
}

extern "C" void kernel_launch(void* const* d_in, const int* in_sizes, int n_in,
                              void* d_out, int out_size) {
    const float* cont    = (const float*)d_in[0];
    const int*   cat     = (const int*)  d_in[1];
    const float* w_cont  = (const float*)d_in[2];
    const float* b_cont  = (const float*)d_in[3];
    const float* t_first = (const float*)d_in[4];
    const float* t_emb   = (const float*)d_in[5];
    const float* W1      = (const float*)d_in[6];
    const float* b1      = (const float*)d_in[7];
    const float* W2      = (const float*)d_in[8];
    const float* b2      = (const float*)d_in[9];
    const float* Wout    = (const float*)d_in[10];
    const float* bout    = (const float*)d_in[11];
    float* out = (float*)d_out;

    const int SMEM_DYN = 2 * STAGE_;
    cudaFuncSetAttribute(gemm_fp16<false>, cudaFuncAttributeMaxDynamicSharedMemorySize, SMEM_DYN);
    cudaFuncSetAttribute(gemm_fp16<true>,  cudaFuncAttributeMaxDynamicSharedMemorySize, SMEM_DYN);

    __half* dnn = (__half*)sym_addr(g_dnn);
    __half* h1  = (__half*)sym_addr(g_h1);
    __half* w1t = (__half*)sym_addr(g_w1t);
    __half* w2t = (__half*)sym_addr(g_w2t);

    // 1) weight prep (transpose + pad + fp16 round)
    prep_kernel<<<(H_ * LDA1_ + 255) / 256, 256>>>(W1, W2);

    // 2) gather + FM + dnn_in (fp16)
    gather_fm_kernel<<<B_ / 8, 256>>>(cont, cat, w_cont, b_cont, t_first, t_emb);

    // 3) h1 = relu(dnn_in @ W1 + b1)     grid: 5 N-tiles x 128 M-tiles
    dim3 grid(5, B_ / 128);
    gemm_fp16<false><<<grid, 256, SMEM_DYN>>>(dnn, w1t, LDA1_,
                                              b1, nullptr, h1, K2PAD_, LDA1_ / 32);

    // 4) fused: h2 = relu(h1 @ W2 + b2); g_part = per-tile dot(h2, Wout[1:])
    gemm_fp16<true><<<grid, 256, SMEM_DYN>>>(h1, w2t, K2PAD_,
                                             b2, Wout, nullptr, 0, K2PAD_ / 32);

    // 5) out = fm*Wout[0] + b_out + parts
    finish_kernel<<<B_ / 256, 256>>>(Wout, bout, out);
}

// round 9
// speedup vs baseline: 6.5537x; 1.1886x over previous
#include <cuda_runtime.h>
#include <cuda_bf16.h>
#include <cuda_fp16.h>
#include <cstdint>

// ---------------- Problem constants ----------------
#define B_     16384
#define F_     26
#define V_     100000
#define E_     16
#define CONT_  13
#define K1_    429     // CONT_ + F_*E_
#define KP_    448     // padded K for BOTH GEMMs (multiple of 64)
#define H_     400
#define NT_    80      // CTA N tile (5 * 80 = 400, exact)

// dnn_in layout (per row, KP_ cols): [ emb 0..415 | cont 416..428 | zero 429..447 ]
// h1 layout: [ h1 0..399 | zero 400..447 ]  (pad never written; zero-init global)

// ---------------- Scratch (device globals) ----------------
__device__ __align__(256) __half g_dnn [(size_t)B_ * KP_];
__device__ __align__(256) __half g_h1  [(size_t)B_ * KP_];
__device__ __align__(256) __half g_w1t [(size_t)H_ * KP_];   // [n][k], k in dnn layout
__device__ __align__(256) __half g_w2t [(size_t)H_ * KP_];   // [n][k] = fp16(W2[k][n])
__device__ float g_fm  [B_];
__device__ float g_part[5][B_];

// ---------------- PTX helpers ----------------
__device__ __forceinline__ uint32_t smem_u32(const void* p) {
    return (uint32_t)__cvta_generic_to_shared(p);
}
#define CP16(dst_u32, src) \
    asm volatile("cp.async.cg.shared.global [%0], [%1], 16;" :: "r"(dst_u32), "l"(src))
#define CP_COMMIT() asm volatile("cp.async.commit_group;" ::: "memory")
#define CP_WAIT0()  asm volatile("cp.async.wait_group 0;" ::: "memory")
#define CP_WAIT1()  asm volatile("cp.async.wait_group 1;" ::: "memory")

#define LDSM_X4(r0, r1, r2, r3, addr)                                          \
    asm volatile("ldmatrix.sync.aligned.m8n8.x4.shared.b16 {%0,%1,%2,%3},[%4];"\
                 : "=r"(r0), "=r"(r1), "=r"(r2), "=r"(r3) : "r"(addr))
#define LDSM_X2(r0, r1, addr)                                                  \
    asm volatile("ldmatrix.sync.aligned.m8n8.x2.shared.b16 {%0,%1},[%2];"      \
                 : "=r"(r0), "=r"(r1) : "r"(addr))

__device__ __forceinline__ void mma_fp16(float* c,
                                         uint32_t a0, uint32_t a1, uint32_t a2, uint32_t a3,
                                         uint32_t b0, uint32_t b1) {
    asm volatile(
        "mma.sync.aligned.m16n8k16.row.col.f32.f16.f16.f32 "
        "{%0,%1,%2,%3},{%4,%5,%6,%7},{%8,%9},{%0,%1,%2,%3};"
        : "+f"(c[0]), "+f"(c[1]), "+f"(c[2]), "+f"(c[3])
        : "r"(a0), "r"(a1), "r"(a2), "r"(a3), "r"(b0), "r"(b1));
}

// ============================================================================
// Kernel 1: gather + FM; emits dnn_in as fp16 (one warp per sample).
//   New layout: lane f writes its 16 fp16 (32B) at col f*16 -> 2 aligned uint4.
// ============================================================================
__global__ void gather_fm_kernel(const float* __restrict__ cont,
                                 const int*   __restrict__ cat,
                                 const float* __restrict__ w_cont,
                                 const float* __restrict__ b_cont,
                                 const float* __restrict__ t_first,
                                 const float* __restrict__ t_emb) {
    int warp = (blockIdx.x * blockDim.x + threadIdx.x) >> 5;
    int lane = threadIdx.x & 31;
    if (warp >= B_) return;
    const int b = warp;

    float v[16];
    #pragma unroll
    for (int i = 0; i < 16; i++) v[i] = 0.f;
    float q = 0.f, scal = 0.f;

    if (lane < F_) {
        int idx = cat[b * F_ + lane];
        const float4* row =
            reinterpret_cast<const float4*>(t_emb + ((size_t)lane * V_ + (size_t)idx) * E_);
        float4 r0 = row[0], r1 = row[1], r2 = row[2], r3 = row[3];
        v[0]=r0.x; v[1]=r0.y; v[2]=r0.z; v[3]=r0.w;
        v[4]=r1.x; v[5]=r1.y; v[6]=r1.z; v[7]=r1.w;
        v[8]=r2.x; v[9]=r2.y; v[10]=r2.z; v[11]=r2.w;
        v[12]=r3.x; v[13]=r3.y; v[14]=r3.z; v[15]=r3.w;

        uint32_t pk[8];
        #pragma unroll
        for (int i = 0; i < 8; i++) {
            __half h0 = __float2half_rn(v[2*i]);
            __half h1 = __float2half_rn(v[2*i+1]);
            pk[i] = (uint32_t)__half_as_ushort(h0) | ((uint32_t)__half_as_ushort(h1) << 16);
            q = fmaf(v[2*i],   v[2*i],   q);
            q = fmaf(v[2*i+1], v[2*i+1], q);
        }
        uint4* dst = reinterpret_cast<uint4*>(g_dnn + (size_t)b * KP_ + lane * E_);
        dst[0] = make_uint4(pk[0], pk[1], pk[2], pk[3]);
        dst[1] = make_uint4(pk[4], pk[5], pk[6], pk[7]);
        scal = t_first[(size_t)lane * V_ + (size_t)idx];
    }
    if (lane < CONT_) {
        float c = cont[b * CONT_ + lane];
        g_dnn[(size_t)b * KP_ + 416 + lane] = __float2half_rn(c);
        scal = fmaf(c, w_cont[lane], scal);
    }
    if (lane < KP_ - K1_) {     // zero cols 429..447 (19 lanes)
        g_dnn[(size_t)b * KP_ + K1_ + lane] = __ushort_as_half((unsigned short)0);
    }

    #pragma unroll
    for (int off = 16; off; off >>= 1) {
        #pragma unroll
        for (int e = 0; e < 16; e++)
            v[e] += __shfl_xor_sync(0xffffffffu, v[e], off);
        q    += __shfl_xor_sync(0xffffffffu, q,    off);
        scal += __shfl_xor_sync(0xffffffffu, scal, off);
    }
    if (lane == 0) {
        float ss = 0.f;
        #pragma unroll
        for (int e = 0; e < 16; e++) ss = fmaf(v[e], v[e], ss);
        g_fm[b] = scal + b_cont[0] + 0.5f * (ss - q);
    }
}

// ============================================================================
// Prep: weights -> fp16 K-major, permuted to dnn layout, padded to KP_
//   W1T[n][k]: k<416 -> W1[13+k][n] (emb), 416<=k<429 -> W1[k-416][n] (cont), else 0
//   W2T[n][k]: k<400 -> W2[k][n], else 0
// ============================================================================
__global__ void prep_kernel(const float* __restrict__ W1, const float* __restrict__ W2) {
    int idx = blockIdx.x * blockDim.x + threadIdx.x;
    if (idx >= H_ * KP_) return;
    int n = idx / KP_, k = idx % KP_;

    float v1;
    if (k < 416)      v1 = W1[(size_t)(CONT_ + k) * H_ + n];
    else if (k < 429) v1 = W1[(size_t)(k - 416) * H_ + n];
    else              v1 = 0.f;
    g_w1t[idx] = __float2half_rn(v1);

    float v2 = (k < H_) ? W2[(size_t)k * H_ + n] : 0.f;
    g_w2t[idx] = __float2half_rn(v2);
}

// ============================================================================
// fp16 GEMM via mma.sync m16n8k16. CTA 128(M) x 80(N), 8 warps (4M x 2N),
//   warp tile 32x40. BK=64, K=448 (7 k-blocks), double-buffered cp.async.
//   SMEM rows 144B (128B data + 16 pad) -> conflict-free ldmatrix.
//   FUSE=0: relu(+bias) -> C fp16.  FUSE=1: fused dot w/ Wout -> g_part.
// ============================================================================
#define ROWB_  144
#define OFF_A  0
#define OFF_B  (128 * ROWB_)          // 18432
#define STAGE_ ((128 + 80) * ROWB_)   // 29952
#define NKB_   (KP_ / 64)             // 7

template<bool FUSE>
__global__ void __launch_bounds__(256, 2)
gemm_fp16(const __half* __restrict__ A,
          const __half* __restrict__ Bh,
          const float* __restrict__ bias,    // [H_]
          const float* __restrict__ Wout,    // [1+H_] (FUSE)
          __half* __restrict__ C) {          // [B_, KP_] (!FUSE)
    extern __shared__ char smem_raw[];
    __shared__ float part[2][128];
    const uint32_t sbase = smem_u32(smem_raw);

    const int tid  = threadIdx.x;
    const int warp = tid >> 5, lane = tid & 31;
    const int gr = lane >> 2, gc = lane & 3;
    const int wm  = (warp >> 1) * 32;    // warp row band (0..96)
    const int wni = warp & 1;
    const int wn  = wni * 40;            // warp col band (0 or 40)
    const int m0 = blockIdx.y * 128;
    const int n0 = blockIdx.x * NT_;

    const int lane8 = lane & 7;
    const int laneH = (lane >> 3) & 1;
    const int laneK = lane >> 4;
    const uint32_t aoff  = (uint32_t)((wm + lane8 + laneH * 8) * ROWB_ + laneK * 16);
    const uint32_t boff4 = (uint32_t)((wn + lane8 + laneK * 8) * ROWB_ + laneH * 16);
    const uint32_t boff2 = (uint32_t)((wn + 32 + lane8) * ROWB_ + laneH * 16);

    float acc[2][5][4];
    #pragma unroll
    for (int i = 0; i < 2; i++)
        #pragma unroll
        for (int j = 0; j < 5; j++)
            #pragma unroll
            for (int k = 0; k < 4; k++) acc[i][j][k] = 0.f;

    // ---- tile loader: A 1024 chunks (4/thread), B 640 chunks (2 + pred) ----
    #define LOAD_KB(KB, BUF)                                                        \
    do {                                                                            \
        const int k0_ = (KB) * 64;                                                  \
        const uint32_t st_ = sbase + (BUF) * STAGE_;                                \
        _Pragma("unroll")                                                           \
        for (int h = 0; h < 4; h++) {                                               \
            int c_ = tid + h * 256;                                                 \
            int row_ = c_ >> 3, q_ = c_ & 7;                                        \
            CP16(st_ + OFF_A + row_ * ROWB_ + q_ * 16,                              \
                 A + (size_t)(m0 + row_) * KP_ + k0_ + q_ * 8);                     \
        }                                                                           \
        _Pragma("unroll")                                                           \
        for (int h = 0; h < 2; h++) {                                               \
            int c_ = tid + h * 256;                                                 \
            int row_ = c_ >> 3, q_ = c_ & 7;                                        \
            CP16(st_ + OFF_B + row_ * ROWB_ + q_ * 16,                              \
                 Bh + (size_t)(n0 + row_) * KP_ + k0_ + q_ * 8);                    \
        }                                                                           \
        if (tid < 128) {                                                            \
            int c_ = 512 + tid;                                                     \
            int row_ = c_ >> 3, q_ = c_ & 7;                                        \
            CP16(st_ + OFF_B + row_ * ROWB_ + q_ * 16,                              \
                 Bh + (size_t)(n0 + row_) * KP_ + k0_ + q_ * 8);                    \
        }                                                                           \
    } while (0)

    LOAD_KB(0, 0);
    CP_COMMIT();

    for (int kb = 0; kb < NKB_; kb++) {
        const int buf = kb & 1;
        if (kb + 1 < NKB_) { LOAD_KB(kb + 1, buf ^ 1); CP_COMMIT(); CP_WAIT1(); }
        else               { CP_WAIT0(); }
        __syncthreads();

        const uint32_t st = sbase + buf * STAGE_;
        #pragma unroll
        for (int ks = 0; ks < 4; ks++) {
            const uint32_t ko = ks * 32;   // 16 fp16 = 32B
            uint32_t ah[2][4], bh[5][2];
            #pragma unroll
            for (int mi = 0; mi < 2; mi++) {
                uint32_t ad = st + OFF_A + aoff + mi * (16 * ROWB_) + ko;
                LDSM_X4(ah[mi][0], ah[mi][1], ah[mi][2], ah[mi][3], ad);
            }
            #pragma unroll
            for (int nj = 0; nj < 2; nj++) {
                uint32_t bd = st + OFF_B + boff4 + nj * (16 * ROWB_) + ko;
                LDSM_X4(bh[nj*2][0], bh[nj*2][1], bh[nj*2+1][0], bh[nj*2+1][1], bd);
            }
            LDSM_X2(bh[4][0], bh[4][1], st + OFF_B + boff2 + ko);

            #pragma unroll
            for (int mi = 0; mi < 2; mi++)
                #pragma unroll
                for (int ni = 0; ni < 5; ni++)
                    mma_fp16(acc[mi][ni], ah[mi][0], ah[mi][1], ah[mi][2], ah[mi][3],
                             bh[ni][0], bh[ni][1]);
        }
        __syncthreads();
    }
    #undef LOAD_KB

    // ---- epilogue (n always < 400: no N checks) ----
    if (!FUSE) {
        #pragma unroll
        for (int mi = 0; mi < 2; mi++) {
            int r = m0 + wm + mi * 16 + gr;
            #pragma unroll
            for (int ni = 0; ni < 5; ni++) {
                int n = n0 + wn + ni * 8 + gc * 2;
                float b0v = bias[n], b1v = bias[n + 1];
                #pragma unroll
                for (int half = 0; half < 2; half++) {
                    float x0 = fmaxf(acc[mi][ni][half * 2 + 0] + b0v, 0.f);
                    float x1 = fmaxf(acc[mi][ni][half * 2 + 1] + b1v, 0.f);
                    __half h0 = __float2half_rn(x0);
                    __half h1 = __float2half_rn(x1);
                    uint32_t ph = (uint32_t)__half_as_ushort(h0) |
                                  ((uint32_t)__half_as_ushort(h1) << 16);
                    size_t o = (size_t)(r + half * 8) * KP_ + n;
                    *reinterpret_cast<uint32_t*>(C + o) = ph;
                }
            }
        }
    } else {
        #pragma unroll
        for (int mi = 0; mi < 2; mi++) {
            float s0 = 0.f, s1 = 0.f;
            #pragma unroll
            for (int ni = 0; ni < 5; ni++) {
                int n = n0 + wn + ni * 8 + gc * 2;
                float w0v = Wout[1 + n], w1v = Wout[2 + n];
                float b0v = bias[n],     b1v = bias[n + 1];
                s0 = fmaf(fmaxf(acc[mi][ni][0] + b0v, 0.f), w0v, s0);
                s0 = fmaf(fmaxf(acc[mi][ni][1] + b1v, 0.f), w1v, s0);
                s1 = fmaf(fmaxf(acc[mi][ni][2] + b0v, 0.f), w0v, s1);
                s1 = fmaf(fmaxf(acc[mi][ni][3] + b1v, 0.f), w1v, s1);
            }
            s0 += __shfl_xor_sync(0xffffffffu, s0, 1);
            s0 += __shfl_xor_sync(0xffffffffu, s0, 2);
            s1 += __shfl_xor_sync(0xffffffffu, s1, 1);
            s1 += __shfl_xor_sync(0xffffffffu, s1, 2);
            if (gc == 0) {
                part[wni][wm + mi * 16 + gr]     = s0;
                part[wni][wm + mi * 16 + gr + 8] = s1;
            }
        }
        __syncthreads();
        if (tid < 128) {
            g_part[blockIdx.x][m0 + tid] = part[0][tid] + part[1][tid];
        }
    }
}

// ============================================================================
// Finish: out[b] = fm[b]*Wout[0] + b_out + sum_p g_part[p][b]
// ============================================================================
__global__ void finish_kernel(const float* __restrict__ Wout,
                              const float* __restrict__ bout,
                              float* __restrict__ out) {
    int b = blockIdx.x * blockDim.x + threadIdx.x;
    if (b >= B_) return;
    float s = g_part[0][b] + g_part[1][b] + g_part[2][b] + g_part[3][b] + g_part[4][b];
    out[b] = fmaf(g_fm[b], Wout[0], bout[0] + s);
}

// ============================================================================
// Launch
// ============================================================================
static void* sym_addr(const void* symbol) {
    void* p = nullptr;
    cudaGetSymbolAddress(&p, symbol);
    return p;
}

extern "C" void kernel_launch(void* const* d_in, const int* in_sizes, int n_in,
                              void* d_out, int out_size) {
    const float* cont    = (const float*)d_in[0];
    const int*   cat     = (const int*)  d_in[1];
    const float* w_cont  = (const float*)d_in[2];
    const float* b_cont  = (const float*)d_in[3];
    const float* t_first = (const float*)d_in[4];
    const float* t_emb   = (const float*)d_in[5];
    const float* W1      = (const float*)d_in[6];
    const float* b1      = (const float*)d_in[7];
    const float* W2      = (const float*)d_in[8];
    const float* b2      = (const float*)d_in[9];
    const float* Wout    = (const float*)d_in[10];
    const float* bout    = (const float*)d_in[11];
    float* out = (float*)d_out;

    const int SMEM_DYN = 2 * STAGE_;
    cudaFuncSetAttribute(gemm_fp16<false>, cudaFuncAttributeMaxDynamicSharedMemorySize, SMEM_DYN);
    cudaFuncSetAttribute(gemm_fp16<true>,  cudaFuncAttributeMaxDynamicSharedMemorySize, SMEM_DYN);

    __half* dnn = (__half*)sym_addr(g_dnn);
    __half* h1  = (__half*)sym_addr(g_h1);
    __half* w1t = (__half*)sym_addr(g_w1t);
    __half* w2t = (__half*)sym_addr(g_w2t);

    // 1) weight prep (transpose + permute + pad + fp16 round)
    prep_kernel<<<(H_ * KP_ + 255) / 256, 256>>>(W1, W2);

    // 2) gather + FM + dnn_in (fp16, aligned layout)
    gather_fm_kernel<<<B_ / 8, 256>>>(cont, cat, w_cont, b_cont, t_first, t_emb);

    // 3) h1 = relu(dnn_in @ W1 + b1)     grid: 5 N-tiles x 128 M-tiles
    dim3 grid(5, B_ / 128);
    gemm_fp16<false><<<grid, 256, SMEM_DYN>>>(dnn, w1t, b1, nullptr, h1);

    // 4) fused: h2 = relu(h1 @ W2 + b2); g_part = per-tile dot(h2, Wout[1:])
    gemm_fp16<true><<<grid, 256, SMEM_DYN>>>(h1, w2t, b2, Wout, nullptr);

    // 5) out = fm*Wout[0] + b_out + parts
    finish_kernel<<<B_ / 256, 256>>>(Wout, bout, out);
}

// round 10
// speedup vs baseline: 6.6162x; 1.0095x over previous
#include <cuda_runtime.h>
#include <cuda_bf16.h>
#include <cuda_fp16.h>
#include <cstdint>

// ---------------- Problem constants ----------------
#define B_     16384
#define F_     26
#define V_     100000
#define E_     16
#define CONT_  13
#define K1_    429     // CONT_ + F_*E_
#define KP1_   448     // dnn_in K padded (mult of 64)
#define KP2_   416     // h1 K padded (mult of 32)
#define H_     400
#define NT_    80      // CTA N tile (5 * 80 = 400, exact)

// dnn_in layout (KP1_): [ emb 0..415 | cont 416..428 | zero 429..447 ]
// h1 layout (KP2_):     [ h1 0..399 | zero 400..415 ]  (pad never written)

// ---------------- Scratch (device globals) ----------------
__device__ __align__(256) __half g_dnn [(size_t)B_ * KP1_];
__device__ __align__(256) __half g_h1  [(size_t)B_ * KP2_];
__device__ __align__(256) __half g_w1t [(size_t)H_ * KP1_];
__device__ __align__(256) __half g_w2t [(size_t)H_ * KP2_];
__device__ float g_fm  [B_];
__device__ float g_part[5][B_];

// ---------------- PTX helpers ----------------
__device__ __forceinline__ uint32_t smem_u32(const void* p) {
    return (uint32_t)__cvta_generic_to_shared(p);
}
#define CP16(dst_u32, src) \
    asm volatile("cp.async.cg.shared.global [%0], [%1], 16;" :: "r"(dst_u32), "l"(src))
#define CP_COMMIT() asm volatile("cp.async.commit_group;" ::: "memory")
#define CP_WAIT0()  asm volatile("cp.async.wait_group 0;" ::: "memory")
#define CP_WAIT1()  asm volatile("cp.async.wait_group 1;" ::: "memory")

#define LDSM_X4(r0, r1, r2, r3, addr)                                          \
    asm volatile("ldmatrix.sync.aligned.m8n8.x4.shared.b16 {%0,%1,%2,%3},[%4];"\
                 : "=r"(r0), "=r"(r1), "=r"(r2), "=r"(r3) : "r"(addr))
#define LDSM_X2(r0, r1, addr)                                                  \
    asm volatile("ldmatrix.sync.aligned.m8n8.x2.shared.b16 {%0,%1},[%2];"      \
                 : "=r"(r0), "=r"(r1) : "r"(addr))

__device__ __forceinline__ void mma_fp16(float* c,
                                         uint32_t a0, uint32_t a1, uint32_t a2, uint32_t a3,
                                         uint32_t b0, uint32_t b1) {
    asm volatile(
        "mma.sync.aligned.m16n8k16.row.col.f32.f16.f16.f32 "
        "{%0,%1,%2,%3},{%4,%5,%6,%7},{%8,%9},{%0,%1,%2,%3};"
        : "+f"(c[0]), "+f"(c[1]), "+f"(c[2]), "+f"(c[3])
        : "r"(a0), "r"(a1), "r"(a2), "r"(a3), "r"(b0), "r"(b1));
}

// ============================================================================
// Kernel 1: gather + FM; emits dnn_in as fp16 (one warp per sample).
// ============================================================================
__global__ void gather_fm_kernel(const float* __restrict__ cont,
                                 const int*   __restrict__ cat,
                                 const float* __restrict__ w_cont,
                                 const float* __restrict__ b_cont,
                                 const float* __restrict__ t_first,
                                 const float* __restrict__ t_emb) {
    int warp = (blockIdx.x * blockDim.x + threadIdx.x) >> 5;
    int lane = threadIdx.x & 31;
    if (warp >= B_) return;
    const int b = warp;

    float v[16];
    #pragma unroll
    for (int i = 0; i < 16; i++) v[i] = 0.f;
    float q = 0.f, scal = 0.f;

    if (lane < F_) {
        int idx = cat[b * F_ + lane];
        const float4* row =
            reinterpret_cast<const float4*>(t_emb + ((size_t)lane * V_ + (size_t)idx) * E_);
        float4 r0 = row[0], r1 = row[1], r2 = row[2], r3 = row[3];
        v[0]=r0.x; v[1]=r0.y; v[2]=r0.z; v[3]=r0.w;
        v[4]=r1.x; v[5]=r1.y; v[6]=r1.z; v[7]=r1.w;
        v[8]=r2.x; v[9]=r2.y; v[10]=r2.z; v[11]=r2.w;
        v[12]=r3.x; v[13]=r3.y; v[14]=r3.z; v[15]=r3.w;

        uint32_t pk[8];
        #pragma unroll
        for (int i = 0; i < 8; i++) {
            __half h0 = __float2half_rn(v[2*i]);
            __half h1 = __float2half_rn(v[2*i+1]);
            pk[i] = (uint32_t)__half_as_ushort(h0) | ((uint32_t)__half_as_ushort(h1) << 16);
            q = fmaf(v[2*i],   v[2*i],   q);
            q = fmaf(v[2*i+1], v[2*i+1], q);
        }
        uint4* dst = reinterpret_cast<uint4*>(g_dnn + (size_t)b * KP1_ + lane * E_);
        dst[0] = make_uint4(pk[0], pk[1], pk[2], pk[3]);
        dst[1] = make_uint4(pk[4], pk[5], pk[6], pk[7]);
        scal = t_first[(size_t)lane * V_ + (size_t)idx];
    }
    if (lane < CONT_) {
        float c = cont[b * CONT_ + lane];
        g_dnn[(size_t)b * KP1_ + 416 + lane] = __float2half_rn(c);
        scal = fmaf(c, w_cont[lane], scal);
    }
    if (lane < KP1_ - K1_) {     // zero cols 429..447 (19 lanes)
        g_dnn[(size_t)b * KP1_ + K1_ + lane] = __ushort_as_half((unsigned short)0);
    }

    #pragma unroll
    for (int off = 16; off; off >>= 1) {
        #pragma unroll
        for (int e = 0; e < 16; e++)
            v[e] += __shfl_xor_sync(0xffffffffu, v[e], off);
        q    += __shfl_xor_sync(0xffffffffu, q,    off);
        scal += __shfl_xor_sync(0xffffffffu, scal, off);
    }
    if (lane == 0) {
        float ss = 0.f;
        #pragma unroll
        for (int e = 0; e < 16; e++) ss = fmaf(v[e], v[e], ss);
        g_fm[b] = scal + b_cont[0] + 0.5f * (ss - q);
    }
}

// ============================================================================
// Prep: weights -> fp16 K-major (permuted/padded layouts per GEMM)
// ============================================================================
__global__ void prep_kernel(const float* __restrict__ W1, const float* __restrict__ W2) {
    int idx = blockIdx.x * blockDim.x + threadIdx.x;
    if (idx < H_ * KP1_) {                   // W1T: [400][448] in dnn layout
        int n = idx / KP1_, k = idx % KP1_;
        float v;
        if (k < 416)      v = W1[(size_t)(CONT_ + k) * H_ + n];
        else if (k < 429) v = W1[(size_t)(k - 416) * H_ + n];
        else              v = 0.f;
        g_w1t[idx] = __float2half_rn(v);
    }
    if (idx < H_ * KP2_) {                   // W2T: [400][416]
        int n = idx / KP2_, k = idx % KP2_;
        float v = (k < H_) ? W2[(size_t)k * H_ + n] : 0.f;
        g_w2t[idx] = __float2half_rn(v);
    }
}

// ============================================================================
// fp16 GEMM via mma.sync m16n8k16. CTA 128(M) x 80(N), 4 warps (2M x 2N),
//   warp tile 64x40, 128 threads. Template BK (32/64), double-buffered.
//   SMEM rows ROWB = 2*BK+16 -> conflict-free ldmatrix (both BK).
//   FUSE=0: relu(+bias) -> C fp16.  FUSE=1: fused dot w/ Wout -> g_part.
// ============================================================================
template<int BK, bool FUSE>
__global__ void __launch_bounds__(128)
gemm_fp16(const __half* __restrict__ A,
          const __half* __restrict__ Bh,
          int ldk, int NKB,
          const float* __restrict__ bias,    // [H_]
          const float* __restrict__ Wout,    // [1+H_] (FUSE)
          __half* __restrict__ C, int ldc) { // (!FUSE)
    constexpr int ROWB  = 2 * BK + 16;
    constexpr int CPR   = BK / 8;            // 16B chunks per row
    constexpr int OFFB  = 128 * ROWB;
    constexpr int STAGE = (128 + 80) * ROWB;
    constexpr int NCH   = 208 * CPR;         // chunks per stage
    constexpr int NIT   = (NCH + 127) / 128;

    extern __shared__ char smem_raw[];
    __shared__ float part[2][128];
    const uint32_t sbase = smem_u32(smem_raw);

    const int tid  = threadIdx.x;
    const int warp = tid >> 5, lane = tid & 31;
    const int gr = lane >> 2, gc = lane & 3;
    const int wm  = (warp >> 1) * 64;    // warp row band (0 / 64)
    const int wni = warp & 1;
    const int wn  = wni * 40;            // warp col band (0 / 40)
    const int m0 = blockIdx.y * 128;
    const int n0 = blockIdx.x * NT_;

    const int lane8 = lane & 7;
    const int laneH = (lane >> 3) & 1;
    const int laneK = lane >> 4;
    const uint32_t aoff  = (uint32_t)((wm + lane8 + laneH * 8) * ROWB + laneK * 16);
    const uint32_t boff4 = (uint32_t)((wn + lane8 + laneK * 8) * ROWB + laneH * 16);
    const uint32_t boff2 = (uint32_t)((wn + 32 + lane8) * ROWB + laneH * 16);

    float acc[4][5][4];
    #pragma unroll
    for (int i = 0; i < 4; i++)
        #pragma unroll
        for (int j = 0; j < 5; j++)
            #pragma unroll
            for (int k = 0; k < 4; k++) acc[i][j][k] = 0.f;

    // ---- generic tile loader ----
    #define LOAD_KB(KB, BUF)                                                        \
    do {                                                                            \
        const int k0_ = (KB) * BK;                                                  \
        const uint32_t st_ = sbase + (BUF) * STAGE;                                 \
        _Pragma("unroll")                                                           \
        for (int h = 0; h < NIT; h++) {                                             \
            int c_ = tid + h * 128;                                                 \
            if (NCH % 128 == 0 || c_ < NCH) {                                       \
                int row_ = c_ / CPR, q_ = c_ % CPR;                                 \
                if (row_ < 128) {                                                   \
                    CP16(st_ + row_ * ROWB + q_ * 16,                               \
                         A + (size_t)(m0 + row_) * ldk + k0_ + q_ * 8);             \
                } else {                                                            \
                    int r2_ = row_ - 128;                                           \
                    CP16(st_ + OFFB + r2_ * ROWB + q_ * 16,                         \
                         Bh + (size_t)(n0 + r2_) * ldk + k0_ + q_ * 8);             \
                }                                                                   \
            }                                                                       \
        }                                                                           \
    } while (0)

    LOAD_KB(0, 0);
    CP_COMMIT();

    for (int kb = 0; kb < NKB; kb++) {
        const int buf = kb & 1;
        if (kb + 1 < NKB) { LOAD_KB(kb + 1, buf ^ 1); CP_COMMIT(); CP_WAIT1(); }
        else              { CP_WAIT0(); }
        __syncthreads();

        const uint32_t st = sbase + buf * STAGE;
        #pragma unroll
        for (int ks = 0; ks < BK / 16; ks++) {
            const uint32_t ko = ks * 32;   // 16 fp16 = 32B
            uint32_t ah[4][4], bh[5][2];
            #pragma unroll
            for (int mi = 0; mi < 4; mi++) {
                uint32_t ad = st + aoff + mi * (16 * ROWB) + ko;
                LDSM_X4(ah[mi][0], ah[mi][1], ah[mi][2], ah[mi][3], ad);
            }
            #pragma unroll
            for (int nj = 0; nj < 2; nj++) {
                uint32_t bd = st + OFFB + boff4 + nj * (16 * ROWB) + ko;
                LDSM_X4(bh[nj*2][0], bh[nj*2][1], bh[nj*2+1][0], bh[nj*2+1][1], bd);
            }
            LDSM_X2(bh[4][0], bh[4][1], st + OFFB + boff2 + ko);

            #pragma unroll
            for (int mi = 0; mi < 4; mi++)
                #pragma unroll
                for (int ni = 0; ni < 5; ni++)
                    mma_fp16(acc[mi][ni], ah[mi][0], ah[mi][1], ah[mi][2], ah[mi][3],
                             bh[ni][0], bh[ni][1]);
        }
        __syncthreads();
    }
    #undef LOAD_KB

    // ---- epilogue (n always < 400: no N checks) ----
    if (!FUSE) {
        #pragma unroll
        for (int mi = 0; mi < 4; mi++) {
            int r = m0 + wm + mi * 16 + gr;
            #pragma unroll
            for (int ni = 0; ni < 5; ni++) {
                int n = n0 + wn + ni * 8 + gc * 2;
                float b0v = bias[n], b1v = bias[n + 1];
                #pragma unroll
                for (int half = 0; half < 2; half++) {
                    float x0 = fmaxf(acc[mi][ni][half * 2 + 0] + b0v, 0.f);
                    float x1 = fmaxf(acc[mi][ni][half * 2 + 1] + b1v, 0.f);
                    __half h0 = __float2half_rn(x0);
                    __half h1 = __float2half_rn(x1);
                    uint32_t ph = (uint32_t)__half_as_ushort(h0) |
                                  ((uint32_t)__half_as_ushort(h1) << 16);
                    size_t o = (size_t)(r + half * 8) * ldc + n;
                    *reinterpret_cast<uint32_t*>(C + o) = ph;
                }
            }
        }
    } else {
        #pragma unroll
        for (int mi = 0; mi < 4; mi++) {
            float s0 = 0.f, s1 = 0.f;
            #pragma unroll
            for (int ni = 0; ni < 5; ni++) {
                int n = n0 + wn + ni * 8 + gc * 2;
                float w0v = Wout[1 + n], w1v = Wout[2 + n];
                float b0v = bias[n],     b1v = bias[n + 1];
                s0 = fmaf(fmaxf(acc[mi][ni][0] + b0v, 0.f), w0v, s0);
                s0 = fmaf(fmaxf(acc[mi][ni][1] + b1v, 0.f), w1v, s0);
                s1 = fmaf(fmaxf(acc[mi][ni][2] + b0v, 0.f), w0v, s1);
                s1 = fmaf(fmaxf(acc[mi][ni][3] + b1v, 0.f), w1v, s1);
            }
            s0 += __shfl_xor_sync(0xffffffffu, s0, 1);
            s0 += __shfl_xor_sync(0xffffffffu, s0, 2);
            s1 += __shfl_xor_sync(0xffffffffu, s1, 1);
            s1 += __shfl_xor_sync(0xffffffffu, s1, 2);
            if (gc == 0) {
                part[wni][wm + mi * 16 + gr]     = s0;
                part[wni][wm + mi * 16 + gr + 8] = s1;
            }
        }
        __syncthreads();
        if (tid < 128) {
            g_part[blockIdx.x][m0 + tid] = part[0][tid] + part[1][tid];
        }
    }
}

// ============================================================================
// Finish: out[b] = fm[b]*Wout[0] + b_out + sum_p g_part[p][b]
// ============================================================================
__global__ void finish_kernel(const float* __restrict__ Wout,
                              const float* __restrict__ bout,
                              float* __restrict__ out) {
    int b = blockIdx.x * blockDim.x + threadIdx.x;
    if (b >= B_) return;
    float s = g_part[0][b] + g_part[1][b] + g_part[2][b] + g_part[3][b] + g_part[4][b];
    out[b] = fmaf(g_fm[b], Wout[0], bout[0] + s);
}

// ============================================================================
// Launch
// ============================================================================
static void* sym_addr(const void* symbol) {
    void* p = nullptr;
    cudaGetSymbolAddress(&p, symbol);
    return p;
}

extern "C" void kernel_launch(void* const* d_in, const int* in_sizes, int n_in,
                              void* d_out, int out_size) {
    const float* cont    = (const float*)d_in[0];
    const int*   cat     = (const int*)  d_in[1];
    const float* w_cont  = (const float*)d_in[2];
    const float* b_cont  = (const float*)d_in[3];
    const float* t_first = (const float*)d_in[4];
    const float* t_emb   = (const float*)d_in[5];
    const float* W1      = (const float*)d_in[6];
    const float* b1      = (const float*)d_in[7];
    const float* W2      = (const float*)d_in[8];
    const float* b2      = (const float*)d_in[9];
    const float* Wout    = (const float*)d_in[10];
    const float* bout    = (const float*)d_in[11];
    float* out = (float*)d_out;

    const int SMEM1 = 2 * (208 * (2 * 64 + 16));   // BK=64: 59904
    const int SMEM2 = 2 * (208 * (2 * 32 + 16));   // BK=32: 33280
    cudaFuncSetAttribute((gemm_fp16<64, false>), cudaFuncAttributeMaxDynamicSharedMemorySize, SMEM1);
    cudaFuncSetAttribute((gemm_fp16<32, true>),  cudaFuncAttributeMaxDynamicSharedMemorySize, SMEM2);

    __half* dnn = (__half*)sym_addr(g_dnn);
    __half* h1  = (__half*)sym_addr(g_h1);
    __half* w1t = (__half*)sym_addr(g_w1t);
    __half* w2t = (__half*)sym_addr(g_w2t);

    // 1) weight prep (transpose + permute + pad + fp16 round)
    prep_kernel<<<(H_ * KP1_ + 255) / 256, 256>>>(W1, W2);

    // 2) gather + FM + dnn_in (fp16, aligned layout)
    gather_fm_kernel<<<B_ / 8, 256>>>(cont, cat, w_cont, b_cont, t_first, t_emb);

    // 3) h1 = relu(dnn_in @ W1 + b1)     grid: 5 N-tiles x 128 M-tiles
    dim3 grid(5, B_ / 128);
    gemm_fp16<64, false><<<grid, 128, SMEM1>>>(dnn, w1t, KP1_, KP1_ / 64,
                                               b1, nullptr, h1, KP2_);

    // 4) fused: h2 = relu(h1 @ W2 + b2); g_part = per-tile dot(h2, Wout[1:])
    gemm_fp16<32, true><<<grid, 128, SMEM2>>>(h1, w2t, KP2_, KP2_ / 32,
                                              b2, Wout, nullptr, 0);

    // 5) out = fm*Wout[0] + b_out + parts
    finish_kernel<<<B_ / 256, 256>>>(Wout, bout, out);
}